// round 14
// baseline (speedup 1.0000x reference)
#include <cuda_runtime.h>
#include <cuda_fp16.h>
#include <cstdint>

#define S_ 4
#define B_ 2
#define N_ 1024
#define D_ 1024
#define H_ 16
#define DH_ 64

// ---------------- device scratch (no allocations allowed) -------------------
__device__ __half g_xh[B_ * N_ * D_];                       // 4MB
__device__ __half g_wh[13 * 1024 * 1024];                   // Wq(0-3) Wk(4-7) Wv(8-11) Wo(12)
__device__ __half g_qh[S_ * B_ * N_ * D_];                  // 16MB
__device__ __half g_kh[S_ * B_ * N_ * D_];                  // 16MB
__device__ __half g_vh[S_ * B_ * N_ * D_];                  // 16MB
__device__ __half g_combh[B_ * N_ * D_];                    // 4MB
__device__ float g_meanx[B_ * D_];
__device__ float g_scalars[16];  // [0..7]=gw*coh (b*4+s), [8..11]=gw/H, [12]=scale/temp

// ---------------- helpers ----------------------------------------------------
__device__ __forceinline__ uint32_t smem_u32(const void* p) {
    uint32_t a;
    asm("{ .reg .u64 t; cvta.to.shared.u64 t, %1; cvt.u32.u64 %0, t; }" : "=r"(a) : "l"(p));
    return a;
}
__device__ __forceinline__ void cp16h(uint32_t dst, const __half* src) {
    asm volatile("cp.async.ca.shared.global [%0], [%1], 16;" :: "r"(dst), "l"(src) : "memory");
}
__device__ __forceinline__ void ldm4(uint32_t* r, uint32_t addr) {
    asm volatile("ldmatrix.sync.aligned.m8n8.x4.shared.b16 {%0,%1,%2,%3}, [%4];"
        : "=r"(r[0]), "=r"(r[1]), "=r"(r[2]), "=r"(r[3]) : "r"(addr));
}
__device__ __forceinline__ void ldm2t(uint32_t* r, uint32_t addr) {
    asm volatile("ldmatrix.sync.aligned.m8n8.x2.trans.shared.b16 {%0,%1}, [%2];"
        : "=r"(r[0]), "=r"(r[1]) : "r"(addr));
}
__device__ __forceinline__ void mma16816(float* d, const uint32_t* a, uint32_t b0, uint32_t b1) {
    asm volatile(
        "mma.sync.aligned.m16n8k16.row.col.f32.f16.f16.f32 "
        "{%0,%1,%2,%3}, {%4,%5,%6,%7}, {%8,%9}, {%0,%1,%2,%3};"
        : "+f"(d[0]), "+f"(d[1]), "+f"(d[2]), "+f"(d[3])
        : "r"(a[0]), "r"(a[1]), "r"(a[2]), "r"(a[3]), "r"(b0), "r"(b1));
}
__device__ __forceinline__ uint32_t h2u(__half2 h) { return *(uint32_t*)&h; }
__device__ __forceinline__ __half2 u2h(uint32_t u) { return *(__half2*)&u; }
__device__ __forceinline__ uint4 lds_u4(uint32_t a) {
    uint4 r;
    asm volatile("ld.shared.v4.u32 {%0,%1,%2,%3}, [%4];"
        : "=r"(r.x), "=r"(r.y), "=r"(r.z), "=r"(r.w) : "r"(a));
    return r;
}
__device__ __forceinline__ void sts_u4(uint32_t a, uint4 v) {
    asm volatile("st.shared.v4.u32 [%0], {%1,%2,%3,%4};"
        :: "r"(a), "r"(v.x), "r"(v.y), "r"(v.z), "r"(v.w));
}

// ---------------- merged prep (fp16 round) + colmean -------------------------
__global__ void prepcol_k(const float* __restrict__ x, const float* __restrict__ Wq,
                          const float* __restrict__ Wk, const float* __restrict__ Wv,
                          const float* __restrict__ Wo) {
    __shared__ float part[8][33];
    if (blockIdx.x < 15360) {
        long long idx = ((long long)blockIdx.x * 256 + threadIdx.x) * 4;
        const float* src; __half* dst; long long off;
        if (idx < 2097152)        { src = x;  off = idx;            dst = g_xh; }
        else if (idx < 6291456)   { src = Wq; off = idx - 2097152;  dst = g_wh; }
        else if (idx < 10485760)  { src = Wk; off = idx - 6291456;  dst = g_wh + 4194304; }
        else if (idx < 14680064)  { src = Wv; off = idx - 10485760; dst = g_wh + 8388608; }
        else                      { src = Wo; off = idx - 14680064; dst = g_wh + 12582912; }
        float4 v = *(const float4*)(src + off);
        __half2 h0 = __floats2half2_rn(v.x, v.y), h1 = __floats2half2_rn(v.z, v.w);
        uint2 o; o.x = h2u(h0); o.y = h2u(h1);
        *(uint2*)(dst + off) = o;
    } else {
        int bid = blockIdx.x - 15360;
        int col = bid * 32 + (threadIdx.x & 31);
        int chunk = threadIdx.x >> 5;
        int b = col >> 10, d = col & 1023;
        float sum = 0.f;
        const float* xp = x + (long long)b * N_ * D_ + d + (long long)(chunk * 128) * D_;
        #pragma unroll 8
        for (int n = 0; n < 128; n++) sum += xp[(long long)n * D_];
        part[chunk][threadIdx.x & 31] = sum;
        __syncthreads();
        if (threadIdx.x < 32) {
            float s = 0.f;
            #pragma unroll
            for (int c = 0; c < 8; c++) s += part[c][threadIdx.x];
            g_meanx[bid * 32 + threadIdx.x] = s * (1.0f / N_);
        }
    }
}

// ---------------- gate: coh, gw, fused scalars ------------------------------
__global__ void gate_k(const float* __restrict__ Wg, const float* __restrict__ bg,
                       const float* __restrict__ hyp_w, const float* __restrict__ temp_p) {
    __shared__ float cohs[8];
    int tid = threadIdx.x;
    int w = tid >> 5, lane = tid & 31;
    if (w < 8) {
        int b = w >> 2, s = w & 3;
        float sum = 0.f;
        for (int d = lane; d < D_; d += 32)
            sum += g_meanx[b * D_ + d] * Wg[s * D_ + d];
        for (int o = 16; o; o >>= 1) sum += __shfl_xor_sync(0xffffffffu, sum, o);
        if (lane == 0) cohs[w] = 1.0f / (1.0f + expf(-(sum + bg[s])));
    }
    __syncthreads();
    if (tid == 0) {
        float t = fminf(fmaxf(temp_p[0], 0.1f), 10.0f);
        float e[S_], mx = -1e30f;
        for (int s = 0; s < S_; s++) { e[s] = hyp_w[s] / t; mx = fmaxf(mx, e[s]); }
        float den = 0.f;
        for (int s = 0; s < S_; s++) { e[s] = expf(e[s] - mx); den += e[s]; }
        for (int s = 0; s < S_; s++) {
            float gw = e[s] / den;
            g_scalars[8 + s] = gw / (float)H_;
            for (int b = 0; b < B_; b++)
                g_scalars[b * 4 + s] = gw * cohs[b * 4 + s];
        }
        g_scalars[12] = 0.125f / t;   // DH^-0.5 / temp
    }
}

// ---------------- zero amean half of d_out -----------------------------------
__global__ void zero2_k(float* __restrict__ outp) {
    long long idx = ((long long)blockIdx.x * 256 + threadIdx.x) * 4;
    *(float4*)(outp + idx) = make_float4(0.f, 0.f, 0.f, 0.f);
}

// ---------------- fp16 HMMA GEMM (projections): 2-stage (R8-proven) ---------
template<int MODE>
__global__ void __launch_bounds__(256) hgemm_k(float* __restrict__ outp,
                                               const float* __restrict__ bias)
{
    constexpr int STAGE = 256 * 128;
    extern __shared__ char smem[];
    uint32_t smb = smem_u32(smem);

    int tid = threadIdx.x, lane = tid & 31, wid = tid >> 5;
    int warpM = wid & 3, warpN = wid >> 2;
    int n0 = blockIdx.x * 128, m0 = blockIdx.y * 128, z = blockIdx.z;

    const __half *Ag, *Bg;
    if (MODE == 0) { Ag = g_xh; Bg = g_wh + ((long long)z << 20); }
    else           { Ag = g_combh; Bg = g_wh + (12LL << 20); }

    float acc[2][8][4];
    #pragma unroll
    for (int mf = 0; mf < 2; mf++)
        #pragma unroll
        for (int nf = 0; nf < 8; nf++)
            #pragma unroll
            for (int i = 0; i < 4; i++) acc[mf][nf][i] = 0.f;

    auto issue = [&](int t) {
        const __half* ap = Ag + (long long)m0 * 1024 + t * 64;
        const __half* bp = Bg + (long long)n0 * 1024 + t * 64;
        uint32_t sa  = smb + (t & 1) * STAGE;
        uint32_t sbb = sa + 128 * 128;
        #pragma unroll
        for (int i = 0; i < 4; i++) {
            int c = tid + 256 * i, row = c >> 3, ch = c & 7;
            cp16h(sa + ((row * 128 + ch * 16) ^ ((row & 7) << 4)),
                  ap + (long long)row * 1024 + ch * 8);
        }
        #pragma unroll
        for (int i = 0; i < 4; i++) {
            int c = tid + 256 * i, row = c >> 3, ch = c & 7;
            cp16h(sbb + ((row * 128 + ch * 16) ^ ((row & 7) << 4)),
                  bp + (long long)row * 1024 + ch * 8);
        }
        asm volatile("cp.async.commit_group;" ::: "memory");
    };

    issue(0);
    for (int t = 0; t < 16; t++) {
        if (t + 1 < 16) {
            issue(t + 1);
            asm volatile("cp.async.wait_group 1;" ::: "memory");
        } else {
            asm volatile("cp.async.wait_group 0;" ::: "memory");
        }
        __syncthreads();
        uint32_t sa = smb + (t & 1) * STAGE, sbb = sa + 128 * 128;
        #pragma unroll
        for (int kk = 0; kk < 4; kk++) {
            uint32_t af[2][4], bf[4][4];
            #pragma unroll
            for (int mf = 0; mf < 2; mf++) {
                int row = warpM * 32 + mf * 16 + (lane & 15);
                uint32_t off = row * 128 + kk * 32 + ((lane >> 4) << 4);
                ldm4(af[mf], sa + (off ^ ((row & 7) << 4)));
            }
            #pragma unroll
            for (int nb = 0; nb < 4; nb++) {
                int row = warpN * 64 + nb * 16 + (lane & 15);
                uint32_t off = row * 128 + kk * 32 + ((lane >> 4) << 4);
                ldm4(bf[nb], sbb + (off ^ ((row & 7) << 4)));
            }
            #pragma unroll
            for (int mf = 0; mf < 2; mf++)
                #pragma unroll
                for (int nf = 0; nf < 8; nf++)
                    mma16816(acc[mf][nf], af[mf], bf[nf >> 1][nf & 1], bf[nf >> 1][(nf & 1) + 2]);
        }
        __syncthreads();
    }

    int r4 = lane >> 2, c4l = lane & 3;
    if (MODE == 0) {
        int w_ = z >> 2, s_ = z & 3;
        __half* C = (w_ == 0 ? g_qh : (w_ == 1 ? g_kh : g_vh)) + ((long long)s_ << 21);
        #pragma unroll
        for (int mf = 0; mf < 2; mf++)
            #pragma unroll
            for (int nf = 0; nf < 8; nf++)
                #pragma unroll
                for (int hf = 0; hf < 2; hf++) {
                    int row = m0 + warpM * 32 + mf * 16 + r4 + hf * 8;
                    int col = n0 + warpN * 64 + nf * 8 + c4l * 2;
                    __half2 hv = __floats2half2_rn(acc[mf][nf][hf * 2], acc[mf][nf][hf * 2 + 1]);
                    *(__half2*)(C + (long long)row * 1024 + col) = hv;
                }
    } else {
        #pragma unroll
        for (int mf = 0; mf < 2; mf++)
            #pragma unroll
            for (int nf = 0; nf < 8; nf++)
                #pragma unroll
                for (int hf = 0; hf < 2; hf++) {
                    int row = m0 + warpM * 32 + mf * 16 + r4 + hf * 8;
                    int col = n0 + warpN * 64 + nf * 8 + c4l * 2;
                    float2 o;
                    o.x = acc[mf][nf][hf * 2]     + bias[col];
                    o.y = acc[mf][nf][hf * 2 + 1] + bias[col + 1];
                    *(float2*)(outp + (long long)row * 1024 + col) = o;
                }
    }
}

// ---------------- fused attention v8: single-pass scores+PV, e in regs ------
// grid (32, 16, 2) = (it, h, b), 256 threads. smem layout as v5 (231,168 B).
// Tile stream per s: [Q, K0,V0, K1,V1, ... K7,V7] (17 tiles).
// Rounds: Q-round (consume 1, issue 1, wait_group 5); 8 KV rounds
// (consume 2, issue 2, wait_group 4). Post-read __syncthreads before issue.
#define AME_SCALE 256.0f
__global__ void __launch_bounds__(256) fused_attn8_k(float* __restrict__ amean_out) {
    extern __shared__ char smem[];
    uint32_t smb = smem_u32(smem);
    const uint32_t STRIP = smb;
    const uint32_t AMEH  = smb + 65536;
    const uint32_t RING  = smb + 131584;
    float* lred = (float*)(smem + 229888);
    float* linv = (float*)(smem + 231040);

    int tid = threadIdx.x, lane = tid & 31, wid = tid >> 5;
    int it = blockIdx.x, h = blockIdx.y, b = blockIdx.z;
    int i0 = it * 32;
    int r4 = lane >> 2, c4l = lane & 3, c2 = c4l * 2;

    for (int i = tid; i < 16512; i += 256)
        asm volatile("st.shared.b32 [%0], %1;" :: "r"(AMEH + i * 4), "r"(0u));
    __syncthreads();

    float alpha = g_scalars[12];
    float oacc[2][8][4];
    #pragma unroll
    for (int mf = 0; mf < 2; mf++)
        #pragma unroll
        for (int nf = 0; nf < 8; nf++)
            #pragma unroll
            for (int i = 0; i < 4; i++) oacc[mf][nf][i] = 0.f;

    // tile stream: g = s*17 + t; t=0 -> Q, odd t -> K((t-1)/2), even t>0 -> V(t/2-1)
    auto issue_g = [&](int g) {
        if (g < 68) {
            int s = g / 17, t = g - s * 17;
            long long sbase = ((long long)(s * B_ + b)) << 20;
            uint32_t dst = RING + (uint32_t)(g % 6) * 16384;
            if (t == 0) {
                const __half* src = g_qh + sbase + (long long)i0 * 1024 + h * 64;
                int r = tid >> 3, c = tid & 7;
                cp16h(dst + ((r * 128 + c * 16) ^ ((r & 7) << 4)),
                      src + (long long)r * 1024 + c * 8);
            } else {
                int jt = (t - 1) >> 1;
                const __half* base = ((t & 1) ? g_kh : g_vh) + sbase + h * 64;
                const __half* src = base + (long long)jt * 128 * 1024;
                #pragma unroll
                for (int i = 0; i < 4; i++) {
                    int idx = tid + 256 * i, r = idx >> 3, c = idx & 7;
                    cp16h(dst + ((r * 128 + c * 16) ^ ((r & 7) << 4)),
                          src + (long long)r * 1024 + c * 8);
                }
            }
        }
        asm volatile("cp.async.commit_group;" ::: "memory");
    };

    for (int g = 0; g < 6; g++) issue_g(g);
    int gi = 6;

    for (int s = 0; s < S_; s++) {
        float ga = g_scalars[8 + s], wsb = g_scalars[b * 4 + s];
        int gbase = s * 17;

        // ---- Q round: consume 1, issue 1 ----
        asm volatile("cp.async.wait_group 5;" ::: "memory");
        __syncthreads();
        uint32_t qf[4][2][4];
        {
            uint32_t qslot = RING + (uint32_t)(gbase % 6) * 16384;
            #pragma unroll
            for (int kk = 0; kk < 4; kk++)
                #pragma unroll
                for (int mf = 0; mf < 2; mf++) {
                    int r = mf * 16 + (lane & 15);
                    ldm4(qf[kk][mf],
                         qslot + ((r * 128 + kk * 32 + ((lane >> 4) << 4)) ^ ((r & 7) << 4)));
                }
        }
        __syncthreads();
        issue_g(gi++);

        // per-s unnormalized O accumulator + l partials
        float os[2][8][4];
        #pragma unroll
        for (int mf = 0; mf < 2; mf++)
            #pragma unroll
            for (int nf = 0; nf < 8; nf++)
                #pragma unroll
                for (int i = 0; i < 4; i++) os[mf][nf][i] = 0.f;
        float l_part[4] = {0.f, 0.f, 0.f, 0.f};

        // ---- KV rounds: scores -> exp(regs) -> strip(amean) + PV mma ----
        for (int jt = 0; jt < 8; jt++) {
            asm volatile("cp.async.wait_group 4;" ::: "memory");
            __syncthreads();
            uint32_t kb = RING + (uint32_t)((gbase + 1 + 2 * jt) % 6) * 16384;
            uint32_t vb = RING + (uint32_t)((gbase + 2 + 2 * jt) % 6) * 16384;

            float sacc[2][2][4];
            #pragma unroll
            for (int mf = 0; mf < 2; mf++)
                #pragma unroll
                for (int nb = 0; nb < 2; nb++)
                    #pragma unroll
                    for (int i = 0; i < 4; i++) sacc[mf][nb][i] = 0.f;
            #pragma unroll
            for (int kk = 0; kk < 4; kk++) {
                uint32_t bf[4];
                int r = wid * 16 + (lane & 15);
                ldm4(bf, kb + ((r * 128 + kk * 32 + ((lane >> 4) << 4)) ^ ((r & 7) << 4)));
                #pragma unroll
                for (int mf = 0; mf < 2; mf++) {
                    mma16816(sacc[mf][0], qf[kk][mf], bf[0], bf[2]);
                    mma16816(sacc[mf][1], qf[kk][mf], bf[1], bf[3]);
                }
            }
            // exp in regs: ef == PV A-fragments (a0..a3) for this warp's 16 j's
            uint32_t ef[2][4];
            #pragma unroll
            for (int mf = 0; mf < 2; mf++)
                #pragma unroll
                for (int nb = 0; nb < 2; nb++)
                    #pragma unroll
                    for (int hf = 0; hf < 2; hf++) {
                        float e0 = __expf(sacc[mf][nb][hf * 2]     * alpha);
                        float e1 = __expf(sacc[mf][nb][hf * 2 + 1] * alpha);
                        l_part[mf * 2 + hf] += e0 + e1;
                        uint32_t pk = h2u(__floats2half2_rn(e0, e1));
                        ef[mf][nb * 2 + hf] = pk;
                        int row = mf * 16 + r4 + hf * 8;
                        uint32_t byte = (uint32_t)((jt * 128 + wid * 16 + nb * 8 + c2) * 2);
                        asm volatile("st.shared.b32 [%0], %1;"
                            :: "r"(STRIP + row * 2048 + (byte ^ ((row & 7) << 4))), "r"(pk));
                    }
            // PV: V fragments for this warp's 16 j's, all 64 d-cols
            int kr = wid * 16 + (lane & 7) + ((lane >> 3) & 1) * 8;
            #pragma unroll
            for (int nf = 0; nf < 8; nf++) {
                uint32_t bf[2];
                ldm2t(bf, vb + ((kr * 128 + nf * 16) ^ ((kr & 7) << 4)));
                #pragma unroll
                for (int mf = 0; mf < 2; mf++)
                    mma16816(os[mf][nf], ef[mf], bf[0], bf[1]);
            }
            __syncthreads();
            issue_g(gi++);
            issue_g(gi++);
        }

        // ---- l reduce: 1/rowsum ----
        #pragma unroll
        for (int i = 0; i < 4; i++) {
            l_part[i] += __shfl_xor_sync(0xffffffffu, l_part[i], 1);
            l_part[i] += __shfl_xor_sync(0xffffffffu, l_part[i], 2);
        }
        if (c4l == 0)
            #pragma unroll
            for (int i = 0; i < 4; i++) lred[(i * 8 + r4) * 9 + wid] = l_part[i];
        __syncthreads();
        if (tid < 32) {
            float sm = 0.f;
            #pragma unroll
            for (int w = 0; w < 8; w++) sm += lred[tid * 9 + w];
            linv[tid] = 1.0f / sm;
        }
        __syncthreads();

        // ---- fold O: oacc += wsb*linv[row] * os (f32) ----
        #pragma unroll
        for (int mf = 0; mf < 2; mf++) {
            float wl0 = wsb * linv[mf * 16 + r4];
            float wl1 = wsb * linv[mf * 16 + r4 + 8];
            #pragma unroll
            for (int nf = 0; nf < 8; nf++) {
                oacc[mf][nf][0] += wl0 * os[mf][nf][0];
                oacc[mf][nf][1] += wl0 * os[mf][nf][1];
                oacc[mf][nf][2] += wl1 * os[mf][nf][2];
                oacc[mf][nf][3] += wl1 * os[mf][nf][3];
            }
        }

        // ---- amean sweep: AMEH += ga*linv[row]*AME_SCALE * strip ----
        {
            int row = tid >> 3, lp = tid & 7;
            __half2 glh = __float2half2_rn(ga * linv[row] * AME_SCALE);
            uint32_t rb = STRIP + row * 2048;
            uint32_t sw = (uint32_t)((row & 7) << 4);
            #pragma unroll
            for (int c = 0; c < 16; c++) {
                uint32_t ad = rb + (((lp + 8 * c) * 16) ^ sw);
                uint4 u = lds_u4(ad);
                uint32_t am = AMEH + (uint32_t)(row * 1032 + (lp + 8 * c) * 8) * 2;
                uint4 a = lds_u4(am);
                a.x = h2u(__hfma2(u2h(u.x), glh, u2h(a.x)));
                a.y = h2u(__hfma2(u2h(u.y), glh, u2h(a.y)));
                a.z = h2u(__hfma2(u2h(u.z), glh, u2h(a.z)));
                a.w = h2u(__hfma2(u2h(u.w), glh, u2h(a.w)));
                sts_u4(am, a);
            }
        }
        // next s's Q-round barrier orders these reads vs strip overwrite
    } // s
    __syncthreads();

    // ---- O: 8 warp partials by logical (row,col), flat reduce ----
    {
        float* scr = (float*)(smem + 131584);   // 64KB, ring is dead
        #pragma unroll
        for (int mf = 0; mf < 2; mf++)
            #pragma unroll
            for (int nf = 0; nf < 8; nf++)
                #pragma unroll
                for (int i = 0; i < 4; i++) {
                    int row = mf * 16 + r4 + (i >> 1) * 8;
                    int col = nf * 8 + c2 + (i & 1);
                    scr[wid * 2048 + row * 64 + col] = oacc[mf][nf][i];
                }
        __syncthreads();
        int row = tid >> 3, colg = (tid & 7) * 8;
        #pragma unroll
        for (int c = 0; c < 8; c += 2) {
            float v0 = 0.f, v1 = 0.f;
            #pragma unroll
            for (int w = 0; w < 8; w++) {
                v0 += scr[w * 2048 + row * 64 + colg + c];
                v1 += scr[w * 2048 + row * 64 + colg + c + 1];
            }
            __half2 hv = __floats2half2_rn(v0, v1);
            *(__half2*)(g_combh + ((long long)b << 20)
                        + (long long)(i0 + row) * 1024 + h * 64 + colg + c) = hv;
        }
    }

    // ---- amean flush: fp16(x256) -> f32 red.add into d_out second half ----
    {
        const float inv_s = 1.0f / AME_SCALE;
        for (int i = tid; i < 8192; i += 256) {
            int row = i >> 8, cc = (i & 255) * 4;
            uint2 u;
            asm volatile("ld.shared.v2.b32 {%0,%1}, [%2];"
                : "=r"(u.x), "=r"(u.y) : "r"(AMEH + (uint32_t)(row * 1032 + cc) * 2));
            float2 f0 = __half22float2(u2h(u.x)), f1 = __half22float2(u2h(u.y));
            float* dst = amean_out + ((long long)(b * 1024 + i0 + row)) * 1024 + cc;
            asm volatile("red.global.add.f32 [%0], %1;" :: "l"(dst),     "f"(f0.x * inv_s));
            asm volatile("red.global.add.f32 [%0], %1;" :: "l"(dst + 1), "f"(f0.y * inv_s));
            asm volatile("red.global.add.f32 [%0], %1;" :: "l"(dst + 2), "f"(f1.x * inv_s));
            asm volatile("red.global.add.f32 [%0], %1;" :: "l"(dst + 3), "f"(f1.y * inv_s));
        }
    }
}

// ---------------- launch ----------------------------------------------------
extern "C" void kernel_launch(void* const* d_in, const int* in_sizes, int n_in,
                              void* d_out, int out_size) {
    const float* x     = (const float*)d_in[0];
    const float* Wq    = (const float*)d_in[1];
    const float* Wk    = (const float*)d_in[2];
    const float* Wv    = (const float*)d_in[3];
    const float* Wg    = (const float*)d_in[4];
    const float* bg    = (const float*)d_in[5];
    const float* Wo    = (const float*)d_in[6];
    const float* bo    = (const float*)d_in[7];
    const float* hyp_w = (const float*)d_in[8];
    const float* temp  = (const float*)d_in[9];
    float* out = (float*)d_out;
    float* out2 = out + (long long)B_ * N_ * D_;

    const int SM_PIPE  = 65536;
    const int SM_FUSED = 231168;

    cudaFuncSetAttribute(hgemm_k<0>, cudaFuncAttributeMaxDynamicSharedMemorySize, SM_PIPE);
    cudaFuncSetAttribute(hgemm_k<3>, cudaFuncAttributeMaxDynamicSharedMemorySize, SM_PIPE);
    cudaFuncSetAttribute(fused_attn8_k, cudaFuncAttributeMaxDynamicSharedMemorySize, SM_FUSED);

    zero2_k<<<2048, 256>>>(out2);
    prepcol_k<<<15424, 256>>>(x, Wq, Wk, Wv, Wo);
    gate_k<<<1, 256>>>(Wg, bg, hyp_w, temp);

    hgemm_k<0><<<dim3(8, 16, 12), 256, SM_PIPE>>>(nullptr, nullptr);

    fused_attn8_k<<<dim3(32, H_, B_), 256, SM_FUSED>>>(out2);

    hgemm_k<3><<<dim3(8, 16, 1), 256, SM_PIPE>>>(out, bo);
}

// round 15
// speedup vs baseline: 1.0159x; 1.0159x over previous
#include <cuda_runtime.h>
#include <cuda_fp16.h>
#include <cstdint>

#define S_ 4
#define B_ 2
#define N_ 1024
#define D_ 1024
#define H_ 16
#define DH_ 64

// ---------------- device scratch (no allocations allowed) -------------------
__device__ __half g_xh[B_ * N_ * D_];                       // 4MB
__device__ __half g_wh[13 * 1024 * 1024];                   // Wq(0-3) Wk(4-7) Wv(8-11) Wo(12)
__device__ __half g_qh[S_ * B_ * N_ * D_];                  // 16MB
__device__ __half g_kh[S_ * B_ * N_ * D_];                  // 16MB
__device__ __half g_vh[S_ * B_ * N_ * D_];                  // 16MB
__device__ __half g_combh[B_ * N_ * D_];                    // 4MB
__device__ float g_meanx[B_ * D_];
__device__ float g_scalars[16];  // [0..7]=gw*coh (b*4+s), [8..11]=gw/H, [12]=scale/temp

// ---------------- helpers ----------------------------------------------------
__device__ __forceinline__ uint32_t smem_u32(const void* p) {
    uint32_t a;
    asm("{ .reg .u64 t; cvta.to.shared.u64 t, %1; cvt.u32.u64 %0, t; }" : "=r"(a) : "l"(p));
    return a;
}
__device__ __forceinline__ void cp16h(uint32_t dst, const __half* src) {
    asm volatile("cp.async.ca.shared.global [%0], [%1], 16;" :: "r"(dst), "l"(src) : "memory");
}
__device__ __forceinline__ void ldm4(uint32_t* r, uint32_t addr) {
    asm volatile("ldmatrix.sync.aligned.m8n8.x4.shared.b16 {%0,%1,%2,%3}, [%4];"
        : "=r"(r[0]), "=r"(r[1]), "=r"(r[2]), "=r"(r[3]) : "r"(addr));
}
__device__ __forceinline__ void ldm2t(uint32_t* r, uint32_t addr) {
    asm volatile("ldmatrix.sync.aligned.m8n8.x2.trans.shared.b16 {%0,%1}, [%2];"
        : "=r"(r[0]), "=r"(r[1]) : "r"(addr));
}
__device__ __forceinline__ void mma16816(float* d, const uint32_t* a, uint32_t b0, uint32_t b1) {
    asm volatile(
        "mma.sync.aligned.m16n8k16.row.col.f32.f16.f16.f32 "
        "{%0,%1,%2,%3}, {%4,%5,%6,%7}, {%8,%9}, {%0,%1,%2,%3};"
        : "+f"(d[0]), "+f"(d[1]), "+f"(d[2]), "+f"(d[3])
        : "r"(a[0]), "r"(a[1]), "r"(a[2]), "r"(a[3]), "r"(b0), "r"(b1));
}
__device__ __forceinline__ uint32_t h2u(__half2 h) { return *(uint32_t*)&h; }
__device__ __forceinline__ __half2 u2h(uint32_t u) { return *(__half2*)&u; }

// ---------------- merged prep (fp16 round) + colmean -------------------------
__global__ void prepcol_k(const float* __restrict__ x, const float* __restrict__ Wq,
                          const float* __restrict__ Wk, const float* __restrict__ Wv,
                          const float* __restrict__ Wo) {
    __shared__ float part[8][33];
    if (blockIdx.x < 15360) {
        long long idx = ((long long)blockIdx.x * 256 + threadIdx.x) * 4;
        const float* src; __half* dst; long long off;
        if (idx < 2097152)        { src = x;  off = idx;            dst = g_xh; }
        else if (idx < 6291456)   { src = Wq; off = idx - 2097152;  dst = g_wh; }
        else if (idx < 10485760)  { src = Wk; off = idx - 6291456;  dst = g_wh + 4194304; }
        else if (idx < 14680064)  { src = Wv; off = idx - 10485760; dst = g_wh + 8388608; }
        else                      { src = Wo; off = idx - 14680064; dst = g_wh + 12582912; }
        float4 v = *(const float4*)(src + off);
        __half2 h0 = __floats2half2_rn(v.x, v.y), h1 = __floats2half2_rn(v.z, v.w);
        uint2 o; o.x = h2u(h0); o.y = h2u(h1);
        *(uint2*)(dst + off) = o;
    } else {
        int bid = blockIdx.x - 15360;
        int col = bid * 32 + (threadIdx.x & 31);
        int chunk = threadIdx.x >> 5;
        int b = col >> 10, d = col & 1023;
        float sum = 0.f;
        const float* xp = x + (long long)b * N_ * D_ + d + (long long)(chunk * 128) * D_;
        #pragma unroll 8
        for (int n = 0; n < 128; n++) sum += xp[(long long)n * D_];
        part[chunk][threadIdx.x & 31] = sum;
        __syncthreads();
        if (threadIdx.x < 32) {
            float s = 0.f;
            #pragma unroll
            for (int c = 0; c < 8; c++) s += part[c][threadIdx.x];
            g_meanx[bid * 32 + threadIdx.x] = s * (1.0f / N_);
        }
    }
}

// ---------------- gate: coh, gw, fused scalars ------------------------------
__global__ void gate_k(const float* __restrict__ Wg, const float* __restrict__ bg,
                       const float* __restrict__ hyp_w, const float* __restrict__ temp_p) {
    __shared__ float cohs[8];
    int tid = threadIdx.x;
    int w = tid >> 5, lane = tid & 31;
    if (w < 8) {
        int b = w >> 2, s = w & 3;
        float sum = 0.f;
        for (int d = lane; d < D_; d += 32)
            sum += g_meanx[b * D_ + d] * Wg[s * D_ + d];
        for (int o = 16; o; o >>= 1) sum += __shfl_xor_sync(0xffffffffu, sum, o);
        if (lane == 0) cohs[w] = 1.0f / (1.0f + expf(-(sum + bg[s])));
    }
    __syncthreads();
    if (tid == 0) {
        float t = fminf(fmaxf(temp_p[0], 0.1f), 10.0f);
        float e[S_], mx = -1e30f;
        for (int s = 0; s < S_; s++) { e[s] = hyp_w[s] / t; mx = fmaxf(mx, e[s]); }
        float den = 0.f;
        for (int s = 0; s < S_; s++) { e[s] = expf(e[s] - mx); den += e[s]; }
        for (int s = 0; s < S_; s++) {
            float gw = e[s] / den;
            g_scalars[8 + s] = gw / (float)H_;
            for (int b = 0; b < B_; b++)
                g_scalars[b * 4 + s] = gw * cohs[b * 4 + s];
        }
        g_scalars[12] = 0.125f / t;   // DH^-0.5 / temp
    }
}

// ---------------- zero amean half of d_out -----------------------------------
__global__ void zero2_k(float* __restrict__ outp) {
    long long idx = ((long long)blockIdx.x * 256 + threadIdx.x) * 4;
    *(float4*)(outp + idx) = make_float4(0.f, 0.f, 0.f, 0.f);
}

// ---------------- fp16 HMMA GEMM (projections): 2-stage (R8-proven) ---------
template<int MODE>
__global__ void __launch_bounds__(256) hgemm_k(float* __restrict__ outp,
                                               const float* __restrict__ bias)
{
    constexpr int STAGE = 256 * 128;
    extern __shared__ char smem[];
    uint32_t smb = smem_u32(smem);

    int tid = threadIdx.x, lane = tid & 31, wid = tid >> 5;
    int warpM = wid & 3, warpN = wid >> 2;
    int n0 = blockIdx.x * 128, m0 = blockIdx.y * 128, z = blockIdx.z;

    const __half *Ag, *Bg;
    if (MODE == 0) { Ag = g_xh; Bg = g_wh + ((long long)z << 20); }
    else           { Ag = g_combh; Bg = g_wh + (12LL << 20); }

    float acc[2][8][4];
    #pragma unroll
    for (int mf = 0; mf < 2; mf++)
        #pragma unroll
        for (int nf = 0; nf < 8; nf++)
            #pragma unroll
            for (int i = 0; i < 4; i++) acc[mf][nf][i] = 0.f;

    auto issue = [&](int t) {
        const __half* ap = Ag + (long long)m0 * 1024 + t * 64;
        const __half* bp = Bg + (long long)n0 * 1024 + t * 64;
        uint32_t sa  = smb + (t & 1) * STAGE;
        uint32_t sbb = sa + 128 * 128;
        #pragma unroll
        for (int i = 0; i < 4; i++) {
            int c = tid + 256 * i, row = c >> 3, ch = c & 7;
            cp16h(sa + ((row * 128 + ch * 16) ^ ((row & 7) << 4)),
                  ap + (long long)row * 1024 + ch * 8);
        }
        #pragma unroll
        for (int i = 0; i < 4; i++) {
            int c = tid + 256 * i, row = c >> 3, ch = c & 7;
            cp16h(sbb + ((row * 128 + ch * 16) ^ ((row & 7) << 4)),
                  bp + (long long)row * 1024 + ch * 8);
        }
        asm volatile("cp.async.commit_group;" ::: "memory");
    };

    issue(0);
    for (int t = 0; t < 16; t++) {
        if (t + 1 < 16) {
            issue(t + 1);
            asm volatile("cp.async.wait_group 1;" ::: "memory");
        } else {
            asm volatile("cp.async.wait_group 0;" ::: "memory");
        }
        __syncthreads();
        uint32_t sa = smb + (t & 1) * STAGE, sbb = sa + 128 * 128;
        #pragma unroll
        for (int kk = 0; kk < 4; kk++) {
            uint32_t af[2][4], bf[4][4];
            #pragma unroll
            for (int mf = 0; mf < 2; mf++) {
                int row = warpM * 32 + mf * 16 + (lane & 15);
                uint32_t off = row * 128 + kk * 32 + ((lane >> 4) << 4);
                ldm4(af[mf], sa + (off ^ ((row & 7) << 4)));
            }
            #pragma unroll
            for (int nb = 0; nb < 4; nb++) {
                int row = warpN * 64 + nb * 16 + (lane & 15);
                uint32_t off = row * 128 + kk * 32 + ((lane >> 4) << 4);
                ldm4(bf[nb], sbb + (off ^ ((row & 7) << 4)));
            }
            #pragma unroll
            for (int mf = 0; mf < 2; mf++)
                #pragma unroll
                for (int nf = 0; nf < 8; nf++)
                    mma16816(acc[mf][nf], af[mf], bf[nf >> 1][nf & 1], bf[nf >> 1][(nf & 1) + 2]);
        }
        __syncthreads();
    }

    int r4 = lane >> 2, c4l = lane & 3;
    if (MODE == 0) {
        int w_ = z >> 2, s_ = z & 3;
        __half* C = (w_ == 0 ? g_qh : (w_ == 1 ? g_kh : g_vh)) + ((long long)s_ << 21);
        #pragma unroll
        for (int mf = 0; mf < 2; mf++)
            #pragma unroll
            for (int nf = 0; nf < 8; nf++)
                #pragma unroll
                for (int hf = 0; hf < 2; hf++) {
                    int row = m0 + warpM * 32 + mf * 16 + r4 + hf * 8;
                    int col = n0 + warpN * 64 + nf * 8 + c4l * 2;
                    __half2 hv = __floats2half2_rn(acc[mf][nf][hf * 2], acc[mf][nf][hf * 2 + 1]);
                    *(__half2*)(C + (long long)row * 1024 + col) = hv;
                }
    } else {
        #pragma unroll
        for (int mf = 0; mf < 2; mf++)
            #pragma unroll
            for (int nf = 0; nf < 8; nf++)
                #pragma unroll
                for (int hf = 0; hf < 2; hf++) {
                    int row = m0 + warpM * 32 + mf * 16 + r4 + hf * 8;
                    int col = n0 + warpN * 64 + nf * 8 + c4l * 2;
                    float2 o;
                    o.x = acc[mf][nf][hf * 2]     + bias[col];
                    o.y = acc[mf][nf][hf * 2 + 1] + bias[col + 1];
                    *(float2*)(outp + (long long)row * 1024 + col) = o;
                }
    }
}

// ---------------- fused attention v9: 16-row tiles, 2 CTAs/SM ---------------
// grid (64, 16, 2) = (it16, h, b), 256 threads.
// smem: STRIP 16x2048B (32,768) | AMEH fp16 16x1032 (33,024) |
//       RING 2x16K (32,768) | lred 16x9 f32 (576) | linv 16 f32 (64) = 99,200
#define AME_SCALE 256.0f
__global__ void __launch_bounds__(256, 2) fused_attn9_k(float* __restrict__ amean_out) {
    extern __shared__ char smem[];
    uint32_t smb = smem_u32(smem);
    const uint32_t STRIP = smb;
    const uint32_t AMEH  = smb + 32768;
    const uint32_t RING  = smb + 65792;
    float* lred = (float*)(smem + 98560);
    float* linv = (float*)(smem + 99136);

    int tid = threadIdx.x, lane = tid & 31, wid = tid >> 5;
    int it = blockIdx.x, h = blockIdx.y, b = blockIdx.z;
    int i0 = it * 16;
    int r4 = lane >> 2, c4l = lane & 3, c2 = c4l * 2;

    // zero amean accumulator (33,024 B)
    for (int i = tid; i < 8256; i += 256)
        asm volatile("st.shared.b32 [%0], %1;" :: "r"(AMEH + i * 4), "r"(0u));
    __syncthreads();

    float alpha = g_scalars[12];
    float oacc[8][4];
    #pragma unroll
    for (int nf = 0; nf < 8; nf++)
        #pragma unroll
        for (int i = 0; i < 4; i++) oacc[nf][i] = 0.f;

    // tile stream: g = s*17 + t; t=0 -> Q(16x64), 1..8 -> K(jt), 9..16 -> V(jt)
    auto issue_g = [&](int g) {
        int s = g / 17, t = g - s * 17;
        long long sbase = ((long long)(s * B_ + b)) << 20;
        uint32_t dst = RING + (uint32_t)(g & 1) * 16384;
        if (t == 0) {
            if (tid < 128) {
                const __half* src = g_qh + sbase + (long long)i0 * 1024 + h * 64;
                int r = tid >> 3, c = tid & 7;
                cp16h(dst + ((r * 128 + c * 16) ^ ((r & 7) << 4)),
                      src + (long long)r * 1024 + c * 8);
            }
        } else {
            const __half* base = ((t <= 8) ? g_kh : g_vh) + sbase + h * 64;
            int jt = (t <= 8) ? (t - 1) : (t - 9);
            const __half* src = base + (long long)jt * 128 * 1024;
            #pragma unroll
            for (int i = 0; i < 4; i++) {
                int idx = tid + 256 * i, r = idx >> 3, c = idx & 7;
                cp16h(dst + ((r * 128 + c * 16) ^ ((r & 7) << 4)),
                      src + (long long)r * 1024 + c * 8);
            }
        }
        asm volatile("cp.async.commit_group;" ::: "memory");
    };

    issue_g(0);
    int gi = 0;

    // round preamble: issue next tile, wait for current, barrier
    auto round_pre = [&]() {
        if (gi + 1 < 68) {
            issue_g(gi + 1);
            asm volatile("cp.async.wait_group 1;" ::: "memory");
        } else {
            asm volatile("cp.async.wait_group 0;" ::: "memory");
        }
        __syncthreads();
    };

    for (int s = 0; s < S_; s++) {
        float ga = g_scalars[8 + s], wsb = g_scalars[b * 4 + s];

        // ---- Q round ----
        round_pre();
        uint32_t qf[4][4];
        {
            uint32_t qslot = RING + (uint32_t)(gi & 1) * 16384;
            #pragma unroll
            for (int kk = 0; kk < 4; kk++) {
                int r = lane & 15;
                ldm4(qf[kk], qslot + ((r * 128 + kk * 32 + ((lane >> 4) << 4)) ^ ((r & 7) << 4)));
            }
        }
        __syncthreads();
        gi++;

        // ---- SCORE rounds (exp in regs, e -> strip, l partials) ----
        float l_part[2] = {0.f, 0.f};
        for (int jt = 0; jt < 8; jt++) {
            round_pre();
            uint32_t kb = RING + (uint32_t)(gi & 1) * 16384;
            float sacc[2][4];
            #pragma unroll
            for (int nb = 0; nb < 2; nb++)
                #pragma unroll
                for (int i = 0; i < 4; i++) sacc[nb][i] = 0.f;
            #pragma unroll
            for (int kk = 0; kk < 4; kk++) {
                uint32_t bf[4];
                int r = wid * 16 + (lane & 15);
                ldm4(bf, kb + ((r * 128 + kk * 32 + ((lane >> 4) << 4)) ^ ((r & 7) << 4)));
                mma16816(sacc[0], qf[kk], bf[0], bf[2]);
                mma16816(sacc[1], qf[kk], bf[1], bf[3]);
            }
            #pragma unroll
            for (int nb = 0; nb < 2; nb++)
                #pragma unroll
                for (int hf = 0; hf < 2; hf++) {
                    float e0 = __expf(sacc[nb][hf * 2]     * alpha);
                    float e1 = __expf(sacc[nb][hf * 2 + 1] * alpha);
                    l_part[hf] += e0 + e1;
                    int row = r4 + hf * 8;
                    uint32_t byte = (uint32_t)((jt * 128 + wid * 16 + nb * 8 + c2) * 2);
                    asm volatile("st.shared.b32 [%0], %1;"
                        :: "r"(STRIP + row * 2048 + (byte ^ ((row & 7) << 4))),
                           "r"(h2u(__floats2half2_rn(e0, e1))));
                }
            __syncthreads();
            gi++;
        }

        // ---- l reduce: 1/rowsum over 16 rows ----
        #pragma unroll
        for (int i = 0; i < 2; i++) {
            l_part[i] += __shfl_xor_sync(0xffffffffu, l_part[i], 1);
            l_part[i] += __shfl_xor_sync(0xffffffffu, l_part[i], 2);
        }
        if (c4l == 0)
            #pragma unroll
            for (int i = 0; i < 2; i++) lred[(i * 8 + r4) * 9 + wid] = l_part[i];
        __syncthreads();
        if (tid < 16) {
            float sm = 0.f;
            #pragma unroll
            for (int w = 0; w < 8; w++) sm += lred[tid * 9 + w];
            linv[tid] = 1.0f / sm;
        }
        __syncthreads();

        __half2 sc0, sc1, gah0, gah1;
        {
            float li0 = linv[r4], li1 = linv[r4 + 8];
            sc0  = __float2half2_rn(wsb * li0);
            sc1  = __float2half2_rn(wsb * li1);
            gah0 = __float2half2_rn(ga * li0 * AME_SCALE);
            gah1 = __float2half2_rn(ga * li1 * AME_SCALE);
        }

        // ---- PV rounds: warp owns jloc = wid*16, all 64 d-cols ----
        int jloc = wid * 16;
        for (int jt = 0; jt < 8; jt++) {
            round_pre();
            uint32_t vb = RING + (uint32_t)(gi & 1) * 16384;

            uint32_t af[4];
            {
                int r = lane & 15;
                uint32_t byte = (uint32_t)((jt * 128 + jloc) * 2) + ((lane >> 4) << 4);
                ldm4(af, STRIP + r * 2048 + (byte ^ ((r & 7) << 4)));
            }
            // amean RMW: this warp's 16-col slice
            {
                int colb = jt * 128 + jloc + c2;
                uint32_t a00 = AMEH + (uint32_t)(r4 * 1032 + colb) * 2;
                uint32_t a10 = AMEH + (uint32_t)((r4 + 8) * 1032 + colb) * 2;
                uint32_t old;
                asm volatile("ld.shared.b32 %0, [%1];" : "=r"(old) : "r"(a00));
                asm volatile("st.shared.b32 [%0], %1;" :: "r"(a00),
                    "r"(h2u(__hfma2(u2h(af[0]), gah0, u2h(old)))));
                asm volatile("ld.shared.b32 %0, [%1];" : "=r"(old) : "r"(a10));
                asm volatile("st.shared.b32 [%0], %1;" :: "r"(a10),
                    "r"(h2u(__hfma2(u2h(af[1]), gah1, u2h(old)))));
                asm volatile("ld.shared.b32 %0, [%1];" : "=r"(old) : "r"(a00 + 16));
                asm volatile("st.shared.b32 [%0], %1;" :: "r"(a00 + 16),
                    "r"(h2u(__hfma2(u2h(af[2]), gah0, u2h(old)))));
                asm volatile("ld.shared.b32 %0, [%1];" : "=r"(old) : "r"(a10 + 16));
                asm volatile("st.shared.b32 [%0], %1;" :: "r"(a10 + 16),
                    "r"(h2u(__hfma2(u2h(af[3]), gah1, u2h(old)))));
            }
            af[0] = h2u(__hmul2(u2h(af[0]), sc0));
            af[1] = h2u(__hmul2(u2h(af[1]), sc1));
            af[2] = h2u(__hmul2(u2h(af[2]), sc0));
            af[3] = h2u(__hmul2(u2h(af[3]), sc1));

            int kr = jloc + (lane & 7) + ((lane >> 3) & 1) * 8;
            #pragma unroll
            for (int nf = 0; nf < 8; nf++) {
                uint32_t bf[2];
                ldm2t(bf, vb + ((kr * 128 + nf * 16) ^ ((kr & 7) << 4)));
                mma16816(oacc[nf], af, bf[0], bf[1]);
            }
            __syncthreads();
            gi++;
        }
    } // s

    // ---- O: 8 warp partials by logical (row,col) in strip area, reduce ----
    {
        float* scr = (float*)smem;   // 32KB, strip dead
        #pragma unroll
        for (int nf = 0; nf < 8; nf++)
            #pragma unroll
            for (int i = 0; i < 4; i++) {
                int row = r4 + (i >> 1) * 8;
                int col = nf * 8 + c2 + (i & 1);
                scr[wid * 1024 + row * 64 + col] = oacc[nf][i];
            }
        __syncthreads();
        int row = tid >> 4, colg = (tid & 15) * 4;
        float v0 = 0.f, v1 = 0.f, v2 = 0.f, v3 = 0.f;
        #pragma unroll
        for (int w = 0; w < 8; w++) {
            v0 += scr[w * 1024 + row * 64 + colg];
            v1 += scr[w * 1024 + row * 64 + colg + 1];
            v2 += scr[w * 1024 + row * 64 + colg + 2];
            v3 += scr[w * 1024 + row * 64 + colg + 3];
        }
        __half* dst = g_combh + ((long long)b << 20) + (long long)(i0 + row) * 1024 + h * 64 + colg;
        *(__half2*)dst       = __floats2half2_rn(v0, v1);
        *(__half2*)(dst + 2) = __floats2half2_rn(v2, v3);
    }

    // ---- amean flush: fp16(x256) -> f32 red.add into d_out second half ----
    {
        const float inv_s = 1.0f / AME_SCALE;
        for (int i = tid; i < 4096; i += 256) {
            int row = i >> 8, cc = (i & 255) * 4;
            uint2 u;
            asm volatile("ld.shared.v2.b32 {%0,%1}, [%2];"
                : "=r"(u.x), "=r"(u.y) : "r"(AMEH + (uint32_t)(row * 1032 + cc) * 2));
            float2 f0 = __half22float2(u2h(u.x)), f1 = __half22float2(u2h(u.y));
            float* dst = amean_out + ((long long)(b * 1024 + i0 + row)) * 1024 + cc;
            asm volatile("red.global.add.f32 [%0], %1;" :: "l"(dst),     "f"(f0.x * inv_s));
            asm volatile("red.global.add.f32 [%0], %1;" :: "l"(dst + 1), "f"(f0.y * inv_s));
            asm volatile("red.global.add.f32 [%0], %1;" :: "l"(dst + 2), "f"(f1.x * inv_s));
            asm volatile("red.global.add.f32 [%0], %1;" :: "l"(dst + 3), "f"(f1.y * inv_s));
        }
    }
}

// ---------------- launch ----------------------------------------------------
extern "C" void kernel_launch(void* const* d_in, const int* in_sizes, int n_in,
                              void* d_out, int out_size) {
    const float* x     = (const float*)d_in[0];
    const float* Wq    = (const float*)d_in[1];
    const float* Wk    = (const float*)d_in[2];
    const float* Wv    = (const float*)d_in[3];
    const float* Wg    = (const float*)d_in[4];
    const float* bg    = (const float*)d_in[5];
    const float* Wo    = (const float*)d_in[6];
    const float* bo    = (const float*)d_in[7];
    const float* hyp_w = (const float*)d_in[8];
    const float* temp  = (const float*)d_in[9];
    float* out = (float*)d_out;
    float* out2 = out + (long long)B_ * N_ * D_;

    const int SM_PIPE  = 65536;
    const int SM_FUSED = 99200;

    cudaFuncSetAttribute(hgemm_k<0>, cudaFuncAttributeMaxDynamicSharedMemorySize, SM_PIPE);
    cudaFuncSetAttribute(hgemm_k<3>, cudaFuncAttributeMaxDynamicSharedMemorySize, SM_PIPE);
    cudaFuncSetAttribute(fused_attn9_k, cudaFuncAttributeMaxDynamicSharedMemorySize, SM_FUSED);

    zero2_k<<<2048, 256>>>(out2);
    prepcol_k<<<15424, 256>>>(x, Wq, Wk, Wv, Wo);
    gate_k<<<1, 256>>>(Wg, bg, hyp_w, temp);

    hgemm_k<0><<<dim3(8, 16, 12), 256, SM_PIPE>>>(nullptr, nullptr);

    fused_attn9_k<<<dim3(64, H_, B_), 256, SM_FUSED>>>(out2);

    hgemm_k<3><<<dim3(8, 16, 1), 256, SM_PIPE>>>(out, bo);
}

// round 16
// speedup vs baseline: 1.0977x; 1.0806x over previous
#include <cuda_runtime.h>
#include <cuda_fp16.h>
#include <cstdint>

#define S_ 4
#define B_ 2
#define N_ 1024
#define D_ 1024
#define H_ 16
#define DH_ 64

// ---------------- device scratch (no allocations allowed) -------------------
__device__ __half g_xh[B_ * N_ * D_];                       // 4MB
__device__ __half g_wh[13 * 1024 * 1024];                   // Wq(0-3) Wk(4-7) Wv(8-11) Wo(12)
__device__ __half g_qh[S_ * B_ * N_ * D_];                  // 16MB (pre-scaled by alpha)
__device__ __half g_kh[S_ * B_ * N_ * D_];                  // 16MB
__device__ __half g_vh[S_ * B_ * N_ * D_];                  // 16MB
__device__ __half g_combh[B_ * N_ * D_];                    // 4MB
__device__ float g_meanx[B_ * D_];
__device__ float g_scalars[16];  // [0..7]=gw*coh (b*4+s), [8..11]=gw/H, [12]=scale/temp

// ---------------- helpers ----------------------------------------------------
__device__ __forceinline__ uint32_t smem_u32(const void* p) {
    uint32_t a;
    asm("{ .reg .u64 t; cvta.to.shared.u64 t, %1; cvt.u32.u64 %0, t; }" : "=r"(a) : "l"(p));
    return a;
}
// L2-only async copy (bypass L1): copies are single-use streaming
__device__ __forceinline__ void cp16g(uint32_t dst, const __half* src) {
    asm volatile("cp.async.cg.shared.global [%0], [%1], 16;" :: "r"(dst), "l"(src) : "memory");
}
__device__ __forceinline__ void ldm4(uint32_t* r, uint32_t addr) {
    asm volatile("ldmatrix.sync.aligned.m8n8.x4.shared.b16 {%0,%1,%2,%3}, [%4];"
        : "=r"(r[0]), "=r"(r[1]), "=r"(r[2]), "=r"(r[3]) : "r"(addr));
}
__device__ __forceinline__ void ldm2t(uint32_t* r, uint32_t addr) {
    asm volatile("ldmatrix.sync.aligned.m8n8.x2.trans.shared.b16 {%0,%1}, [%2];"
        : "=r"(r[0]), "=r"(r[1]) : "r"(addr));
}
__device__ __forceinline__ void mma16816(float* d, const uint32_t* a, uint32_t b0, uint32_t b1) {
    asm volatile(
        "mma.sync.aligned.m16n8k16.row.col.f32.f16.f16.f32 "
        "{%0,%1,%2,%3}, {%4,%5,%6,%7}, {%8,%9}, {%0,%1,%2,%3};"
        : "+f"(d[0]), "+f"(d[1]), "+f"(d[2]), "+f"(d[3])
        : "r"(a[0]), "r"(a[1]), "r"(a[2]), "r"(a[3]), "r"(b0), "r"(b1));
}
__device__ __forceinline__ uint32_t h2u(__half2 h) { return *(uint32_t*)&h; }
__device__ __forceinline__ __half2 u2h(uint32_t u) { return *(__half2*)&u; }

// ---------------- merged prep (fp16 round) + colmean + amean zero ------------
__global__ void prepcol_k(const float* __restrict__ x, const float* __restrict__ Wq,
                          const float* __restrict__ Wk, const float* __restrict__ Wv,
                          const float* __restrict__ Wo, float* __restrict__ out2) {
    __shared__ float part[8][33];
    if (blockIdx.x < 15360) {
        long long idx = ((long long)blockIdx.x * 256 + threadIdx.x) * 4;
        const float* src; __half* dst; long long off;
        if (idx < 2097152)        { src = x;  off = idx;            dst = g_xh; }
        else if (idx < 6291456)   { src = Wq; off = idx - 2097152;  dst = g_wh; }
        else if (idx < 10485760)  { src = Wk; off = idx - 6291456;  dst = g_wh + 4194304; }
        else if (idx < 14680064)  { src = Wv; off = idx - 10485760; dst = g_wh + 8388608; }
        else                      { src = Wo; off = idx - 14680064; dst = g_wh + 12582912; }
        float4 v = *(const float4*)(src + off);
        __half2 h0 = __floats2half2_rn(v.x, v.y), h1 = __floats2half2_rn(v.z, v.w);
        uint2 o; o.x = h2u(h0); o.y = h2u(h1);
        *(uint2*)(dst + off) = o;
    } else if (blockIdx.x < 15424) {
        int bid = blockIdx.x - 15360;
        int col = bid * 32 + (threadIdx.x & 31);
        int chunk = threadIdx.x >> 5;
        int b = col >> 10, d = col & 1023;
        float sum = 0.f;
        const float* xp = x + (long long)b * N_ * D_ + d + (long long)(chunk * 128) * D_;
        #pragma unroll 8
        for (int n = 0; n < 128; n++) sum += xp[(long long)n * D_];
        part[chunk][threadIdx.x & 31] = sum;
        __syncthreads();
        if (threadIdx.x < 32) {
            float s = 0.f;
            #pragma unroll
            for (int c = 0; c < 8; c++) s += part[c][threadIdx.x];
            g_meanx[bid * 32 + threadIdx.x] = s * (1.0f / N_);
        }
    } else {
        long long idx = ((long long)(blockIdx.x - 15424) * 256 + threadIdx.x) * 4;
        *(float4*)(out2 + idx) = make_float4(0.f, 0.f, 0.f, 0.f);
    }
}

// ---------------- gate: coh, gw, fused scalars ------------------------------
__global__ void gate_k(const float* __restrict__ Wg, const float* __restrict__ bg,
                       const float* __restrict__ hyp_w, const float* __restrict__ temp_p) {
    __shared__ float cohs[8];
    int tid = threadIdx.x;
    int w = tid >> 5, lane = tid & 31;
    if (w < 8) {
        int b = w >> 2, s = w & 3;
        float sum = 0.f;
        for (int d = lane; d < D_; d += 32)
            sum += g_meanx[b * D_ + d] * Wg[s * D_ + d];
        for (int o = 16; o; o >>= 1) sum += __shfl_xor_sync(0xffffffffu, sum, o);
        if (lane == 0) cohs[w] = 1.0f / (1.0f + expf(-(sum + bg[s])));
    }
    __syncthreads();
    if (tid == 0) {
        float t = fminf(fmaxf(temp_p[0], 0.1f), 10.0f);
        float e[S_], mx = -1e30f;
        for (int s = 0; s < S_; s++) { e[s] = hyp_w[s] / t; mx = fmaxf(mx, e[s]); }
        float den = 0.f;
        for (int s = 0; s < S_; s++) { e[s] = expf(e[s] - mx); den += e[s]; }
        for (int s = 0; s < S_; s++) {
            float gw = e[s] / den;
            g_scalars[8 + s] = gw / (float)H_;
            for (int b = 0; b < B_; b++)
                g_scalars[b * 4 + s] = gw * cohs[b * 4 + s];
        }
        g_scalars[12] = 0.125f / t;   // DH^-0.5 / temp (folded into Q proj)
    }
}

// ---------------- fp16 HMMA GEMM (projections): 2-stage (R8-proven) ---------
// MODE 0: QKV proj (Q pre-scaled by g_scalars[12]). MODE 3: out proj.
template<int MODE>
__global__ void __launch_bounds__(256) hgemm_k(float* __restrict__ outp,
                                               const float* __restrict__ bias)
{
    constexpr int STAGE = 256 * 128;
    extern __shared__ char smem[];
    uint32_t smb = smem_u32(smem);

    int tid = threadIdx.x, lane = tid & 31, wid = tid >> 5;
    int warpM = wid & 3, warpN = wid >> 2;
    int n0 = blockIdx.x * 128, m0 = blockIdx.y * 128, z = blockIdx.z;

    const __half *Ag, *Bg;
    if (MODE == 0) { Ag = g_xh; Bg = g_wh + ((long long)z << 20); }
    else           { Ag = g_combh; Bg = g_wh + (12LL << 20); }

    float acc[2][8][4];
    #pragma unroll
    for (int mf = 0; mf < 2; mf++)
        #pragma unroll
        for (int nf = 0; nf < 8; nf++)
            #pragma unroll
            for (int i = 0; i < 4; i++) acc[mf][nf][i] = 0.f;

    auto issue = [&](int t) {
        const __half* ap = Ag + (long long)m0 * 1024 + t * 64;
        const __half* bp = Bg + (long long)n0 * 1024 + t * 64;
        uint32_t sa  = smb + (t & 1) * STAGE;
        uint32_t sbb = sa + 128 * 128;
        #pragma unroll
        for (int i = 0; i < 4; i++) {
            int c = tid + 256 * i, row = c >> 3, ch = c & 7;
            cp16g(sa + ((row * 128 + ch * 16) ^ ((row & 7) << 4)),
                  ap + (long long)row * 1024 + ch * 8);
        }
        #pragma unroll
        for (int i = 0; i < 4; i++) {
            int c = tid + 256 * i, row = c >> 3, ch = c & 7;
            cp16g(sbb + ((row * 128 + ch * 16) ^ ((row & 7) << 4)),
                  bp + (long long)row * 1024 + ch * 8);
        }
        asm volatile("cp.async.commit_group;" ::: "memory");
    };

    issue(0);
    for (int t = 0; t < 16; t++) {
        if (t + 1 < 16) {
            issue(t + 1);
            asm volatile("cp.async.wait_group 1;" ::: "memory");
        } else {
            asm volatile("cp.async.wait_group 0;" ::: "memory");
        }
        __syncthreads();
        uint32_t sa = smb + (t & 1) * STAGE, sbb = sa + 128 * 128;
        #pragma unroll
        for (int kk = 0; kk < 4; kk++) {
            uint32_t af[2][4], bf[4][4];
            #pragma unroll
            for (int mf = 0; mf < 2; mf++) {
                int row = warpM * 32 + mf * 16 + (lane & 15);
                uint32_t off = row * 128 + kk * 32 + ((lane >> 4) << 4);
                ldm4(af[mf], sa + (off ^ ((row & 7) << 4)));
            }
            #pragma unroll
            for (int nb = 0; nb < 4; nb++) {
                int row = warpN * 64 + nb * 16 + (lane & 15);
                uint32_t off = row * 128 + kk * 32 + ((lane >> 4) << 4);
                ldm4(bf[nb], sbb + (off ^ ((row & 7) << 4)));
            }
            #pragma unroll
            for (int mf = 0; mf < 2; mf++)
                #pragma unroll
                for (int nf = 0; nf < 8; nf++)
                    mma16816(acc[mf][nf], af[mf], bf[nf >> 1][nf & 1], bf[nf >> 1][(nf & 1) + 2]);
        }
        __syncthreads();
    }

    int r4 = lane >> 2, c4l = lane & 3;
    if (MODE == 0) {
        int w_ = z >> 2, s_ = z & 3;
        float qs = (w_ == 0) ? g_scalars[12] : 1.0f;   // fold alpha into Q
        __half* C = (w_ == 0 ? g_qh : (w_ == 1 ? g_kh : g_vh)) + ((long long)s_ << 21);
        #pragma unroll
        for (int mf = 0; mf < 2; mf++)
            #pragma unroll
            for (int nf = 0; nf < 8; nf++)
                #pragma unroll
                for (int hf = 0; hf < 2; hf++) {
                    int row = m0 + warpM * 32 + mf * 16 + r4 + hf * 8;
                    int col = n0 + warpN * 64 + nf * 8 + c4l * 2;
                    __half2 hv = __floats2half2_rn(acc[mf][nf][hf * 2] * qs,
                                                   acc[mf][nf][hf * 2 + 1] * qs);
                    *(__half2*)(C + (long long)row * 1024 + col) = hv;
                }
    } else {
        #pragma unroll
        for (int mf = 0; mf < 2; mf++)
            #pragma unroll
            for (int nf = 0; nf < 8; nf++)
                #pragma unroll
                for (int hf = 0; hf < 2; hf++) {
                    int row = m0 + warpM * 32 + mf * 16 + r4 + hf * 8;
                    int col = n0 + warpN * 64 + nf * 8 + c4l * 2;
                    float2 o;
                    o.x = acc[mf][nf][hf * 2]     + bias[col];
                    o.y = acc[mf][nf][hf * 2 + 1] + bias[col + 1];
                    *(float2*)(outp + (long long)row * 1024 + col) = o;
                }
    }
}

// ---------------- fused attention v7b: R13 + .cg copies + alpha pre-folded --
// grid (32, 16, 2) = (it, h, b). smem 231,168 B.
#define AME_SCALE 256.0f
__global__ void __launch_bounds__(256) fused_attn7_k(float* __restrict__ amean_out) {
    extern __shared__ char smem[];
    uint32_t smb = smem_u32(smem);
    const uint32_t STRIP = smb;
    const uint32_t AMEH  = smb + 65536;
    const uint32_t RING  = smb + 131584;
    float* lred = (float*)(smem + 229888);
    float* linv = (float*)(smem + 231040);

    int tid = threadIdx.x, lane = tid & 31, wid = tid >> 5;
    int it = blockIdx.x, h = blockIdx.y, b = blockIdx.z;
    int i0 = it * 32;
    int r4 = lane >> 2, c4l = lane & 3, c2 = c4l * 2;

    for (int i = tid; i < 16512; i += 256)
        asm volatile("st.shared.b32 [%0], %1;" :: "r"(AMEH + i * 4), "r"(0u));
    __syncthreads();

    float oacc[2][8][4];
    #pragma unroll
    for (int mf = 0; mf < 2; mf++)
        #pragma unroll
        for (int nf = 0; nf < 8; nf++)
            #pragma unroll
            for (int i = 0; i < 4; i++) oacc[mf][nf][i] = 0.f;

    auto issue_g = [&](int g) {
        if (g < 68) {
            int s = g / 17, t = g - s * 17;
            long long sbase = ((long long)(s * B_ + b)) << 20;
            uint32_t dst = RING + (uint32_t)(g % 6) * 16384;
            if (t == 0) {
                const __half* src = g_qh + sbase + (long long)i0 * 1024 + h * 64;
                int r = tid >> 3, c = tid & 7;
                cp16g(dst + ((r * 128 + c * 16) ^ ((r & 7) << 4)),
                      src + (long long)r * 1024 + c * 8);
            } else {
                const __half* base = ((t <= 8) ? g_kh : g_vh) + sbase + h * 64;
                int jt = (t <= 8) ? (t - 1) : (t - 9);
                const __half* src = base + (long long)jt * 128 * 1024;
                #pragma unroll
                for (int i = 0; i < 4; i++) {
                    int idx = tid + 256 * i, r = idx >> 3, c = idx & 7;
                    cp16g(dst + ((r * 128 + c * 16) ^ ((r & 7) << 4)),
                          src + (long long)r * 1024 + c * 8);
                }
            }
        }
        asm volatile("cp.async.commit_group;" ::: "memory");
    };

    for (int g = 0; g < 5; g++) issue_g(g);
    int gi = 5;

    for (int s = 0; s < S_; s++) {
        float ga = g_scalars[8 + s], wsb = g_scalars[b * 4 + s];
        int gbase = s * 17;

        asm volatile("cp.async.wait_group 4;" ::: "memory");
        __syncthreads();
        issue_g(gi++);
        uint32_t qf[4][2][4];
        {
            uint32_t qslot = RING + (uint32_t)(gbase % 6) * 16384;
            #pragma unroll
            for (int kk = 0; kk < 4; kk++)
                #pragma unroll
                for (int mf = 0; mf < 2; mf++) {
                    int r = mf * 16 + (lane & 15);
                    ldm4(qf[kk][mf],
                         qslot + ((r * 128 + kk * 32 + ((lane >> 4) << 4)) ^ ((r & 7) << 4)));
                }
        }

        // ---- SCORE rounds (alpha pre-folded into q) ----
        float l_part[4] = {0.f, 0.f, 0.f, 0.f};
        for (int jt = 0; jt < 8; jt++) {
            asm volatile("cp.async.wait_group 4;" ::: "memory");
            __syncthreads();
            issue_g(gi++);
            uint32_t kb = RING + (uint32_t)((gbase + 1 + jt) % 6) * 16384;
            float sacc[2][2][4];
            #pragma unroll
            for (int mf = 0; mf < 2; mf++)
                #pragma unroll
                for (int nb = 0; nb < 2; nb++)
                    #pragma unroll
                    for (int i = 0; i < 4; i++) sacc[mf][nb][i] = 0.f;
            #pragma unroll
            for (int kk = 0; kk < 4; kk++) {
                uint32_t bf[4];
                int r = wid * 16 + (lane & 15);
                ldm4(bf, kb + ((r * 128 + kk * 32 + ((lane >> 4) << 4)) ^ ((r & 7) << 4)));
                #pragma unroll
                for (int mf = 0; mf < 2; mf++) {
                    mma16816(sacc[mf][0], qf[kk][mf], bf[0], bf[2]);
                    mma16816(sacc[mf][1], qf[kk][mf], bf[1], bf[3]);
                }
            }
            #pragma unroll
            for (int mf = 0; mf < 2; mf++)
                #pragma unroll
                for (int nb = 0; nb < 2; nb++)
                    #pragma unroll
                    for (int hf = 0; hf < 2; hf++) {
                        float e0 = __expf(sacc[mf][nb][hf * 2]);
                        float e1 = __expf(sacc[mf][nb][hf * 2 + 1]);
                        l_part[mf * 2 + hf] += e0 + e1;
                        int row = mf * 16 + r4 + hf * 8;
                        uint32_t byte = (uint32_t)((jt * 128 + wid * 16 + nb * 8 + c2) * 2);
                        asm volatile("st.shared.b32 [%0], %1;"
                            :: "r"(STRIP + row * 2048 + (byte ^ ((row & 7) << 4))),
                               "r"(h2u(__floats2half2_rn(e0, e1))));
                    }
        }

        // ---- l reduce ----
        #pragma unroll
        for (int i = 0; i < 4; i++) {
            l_part[i] += __shfl_xor_sync(0xffffffffu, l_part[i], 1);
            l_part[i] += __shfl_xor_sync(0xffffffffu, l_part[i], 2);
        }
        if (c4l == 0)
            #pragma unroll
            for (int i = 0; i < 4; i++) lred[(i * 8 + r4) * 9 + wid] = l_part[i];
        __syncthreads();
        if (tid < 32) {
            float sm = 0.f;
            #pragma unroll
            for (int w = 0; w < 8; w++) sm += lred[tid * 9 + w];
            linv[tid] = 1.0f / sm;
        }
        __syncthreads();

        __half2 sc[2][2], gah[2][2];
        #pragma unroll
        for (int mf = 0; mf < 2; mf++) {
            float li0 = linv[mf * 16 + r4], li1 = linv[mf * 16 + r4 + 8];
            sc[mf][0]  = __float2half2_rn(wsb * li0);
            sc[mf][1]  = __float2half2_rn(wsb * li1);
            gah[mf][0] = __float2half2_rn(ga * li0 * AME_SCALE);
            gah[mf][1] = __float2half2_rn(ga * li1 * AME_SCALE);
        }

        // ---- PV rounds: warp owns jloc = wid*16, all 64 d-cols ----
        int jloc = wid * 16;
        for (int jt = 0; jt < 8; jt++) {
            asm volatile("cp.async.wait_group 4;" ::: "memory");
            __syncthreads();
            issue_g(gi++);
            uint32_t vb = RING + (uint32_t)((gbase + 9 + jt) % 6) * 16384;

            uint32_t af[2][4];
            #pragma unroll
            for (int mf = 0; mf < 2; mf++) {
                int r = mf * 16 + (lane & 15);
                uint32_t byte = (uint32_t)((jt * 128 + jloc) * 2) + ((lane >> 4) << 4);
                ldm4(af[mf], STRIP + r * 2048 + (byte ^ ((r & 7) << 4)));
            }
            #pragma unroll
            for (int mf = 0; mf < 2; mf++) {
                int row0 = mf * 16 + r4, row1 = row0 + 8;
                int colb = jt * 128 + jloc + c2;
                uint32_t a00 = AMEH + (uint32_t)(row0 * 1032 + colb) * 2;
                uint32_t a10 = AMEH + (uint32_t)(row1 * 1032 + colb) * 2;
                uint32_t old;
                asm volatile("ld.shared.b32 %0, [%1];" : "=r"(old) : "r"(a00));
                asm volatile("st.shared.b32 [%0], %1;" :: "r"(a00),
                    "r"(h2u(__hfma2(u2h(af[mf][0]), gah[mf][0], u2h(old)))));
                asm volatile("ld.shared.b32 %0, [%1];" : "=r"(old) : "r"(a10));
                asm volatile("st.shared.b32 [%0], %1;" :: "r"(a10),
                    "r"(h2u(__hfma2(u2h(af[mf][1]), gah[mf][1], u2h(old)))));
                asm volatile("ld.shared.b32 %0, [%1];" : "=r"(old) : "r"(a00 + 16));
                asm volatile("st.shared.b32 [%0], %1;" :: "r"(a00 + 16),
                    "r"(h2u(__hfma2(u2h(af[mf][2]), gah[mf][0], u2h(old)))));
                asm volatile("ld.shared.b32 %0, [%1];" : "=r"(old) : "r"(a10 + 16));
                asm volatile("st.shared.b32 [%0], %1;" :: "r"(a10 + 16),
                    "r"(h2u(__hfma2(u2h(af[mf][3]), gah[mf][1], u2h(old)))));
            }
            #pragma unroll
            for (int mf = 0; mf < 2; mf++) {
                af[mf][0] = h2u(__hmul2(u2h(af[mf][0]), sc[mf][0]));
                af[mf][1] = h2u(__hmul2(u2h(af[mf][1]), sc[mf][1]));
                af[mf][2] = h2u(__hmul2(u2h(af[mf][2]), sc[mf][0]));
                af[mf][3] = h2u(__hmul2(u2h(af[mf][3]), sc[mf][1]));
            }
            int kr = jloc + (lane & 7) + ((lane >> 3) & 1) * 8;
            #pragma unroll
            for (int nf = 0; nf < 8; nf++) {
                uint32_t bf[2];
                ldm2t(bf, vb + ((kr * 128 + nf * 16) ^ ((kr & 7) << 4)));
                #pragma unroll
                for (int mf = 0; mf < 2; mf++)
                    mma16816(oacc[mf][nf], af[mf], bf[0], bf[1]);
            }
        }
    } // s
    __syncthreads();

    // ---- O: 8 warp partials by logical (row,col), flat reduce ----
    {
        float* scr = (float*)(smem + 131584);
        #pragma unroll
        for (int mf = 0; mf < 2; mf++)
            #pragma unroll
            for (int nf = 0; nf < 8; nf++)
                #pragma unroll
                for (int i = 0; i < 4; i++) {
                    int row = mf * 16 + r4 + (i >> 1) * 8;
                    int col = nf * 8 + c2 + (i & 1);
                    scr[wid * 2048 + row * 64 + col] = oacc[mf][nf][i];
                }
        __syncthreads();
        int row = tid >> 3, colg = (tid & 7) * 8;
        #pragma unroll
        for (int c = 0; c < 8; c += 2) {
            float v0 = 0.f, v1 = 0.f;
            #pragma unroll
            for (int w = 0; w < 8; w++) {
                v0 += scr[w * 2048 + row * 64 + colg + c];
                v1 += scr[w * 2048 + row * 64 + colg + c + 1];
            }
            __half2 hv = __floats2half2_rn(v0, v1);
            *(__half2*)(g_combh + ((long long)b << 20)
                        + (long long)(i0 + row) * 1024 + h * 64 + colg + c) = hv;
        }
    }

    // ---- amean flush: fp16(x256) -> f32 red.add ----
    {
        const float inv_s = 1.0f / AME_SCALE;
        for (int i = tid; i < 8192; i += 256) {
            int row = i >> 8, cc = (i & 255) * 4;
            uint2 u;
            asm volatile("ld.shared.v2.b32 {%0,%1}, [%2];"
                : "=r"(u.x), "=r"(u.y) : "r"(AMEH + (uint32_t)(row * 1032 + cc) * 2));
            float2 f0 = __half22float2(u2h(u.x)), f1 = __half22float2(u2h(u.y));
            float* dst = amean_out + ((long long)(b * 1024 + i0 + row)) * 1024 + cc;
            asm volatile("red.global.add.f32 [%0], %1;" :: "l"(dst),     "f"(f0.x * inv_s));
            asm volatile("red.global.add.f32 [%0], %1;" :: "l"(dst + 1), "f"(f0.y * inv_s));
            asm volatile("red.global.add.f32 [%0], %1;" :: "l"(dst + 2), "f"(f1.x * inv_s));
            asm volatile("red.global.add.f32 [%0], %1;" :: "l"(dst + 3), "f"(f1.y * inv_s));
        }
    }
}

// ---------------- launch ----------------------------------------------------
extern "C" void kernel_launch(void* const* d_in, const int* in_sizes, int n_in,
                              void* d_out, int out_size) {
    const float* x     = (const float*)d_in[0];
    const float* Wq    = (const float*)d_in[1];
    const float* Wk    = (const float*)d_in[2];
    const float* Wv    = (const float*)d_in[3];
    const float* Wg    = (const float*)d_in[4];
    const float* bg    = (const float*)d_in[5];
    const float* Wo    = (const float*)d_in[6];
    const float* bo    = (const float*)d_in[7];
    const float* hyp_w = (const float*)d_in[8];
    const float* temp  = (const float*)d_in[9];
    float* out = (float*)d_out;
    float* out2 = out + (long long)B_ * N_ * D_;

    const int SM_PIPE  = 65536;
    const int SM_FUSED = 231168;

    cudaFuncSetAttribute(hgemm_k<0>, cudaFuncAttributeMaxDynamicSharedMemorySize, SM_PIPE);
    cudaFuncSetAttribute(hgemm_k<3>, cudaFuncAttributeMaxDynamicSharedMemorySize, SM_PIPE);
    cudaFuncSetAttribute(fused_attn7_k, cudaFuncAttributeMaxDynamicSharedMemorySize, SM_FUSED);

    prepcol_k<<<17472, 256>>>(x, Wq, Wk, Wv, Wo, out2);
    gate_k<<<1, 256>>>(Wg, bg, hyp_w, temp);

    hgemm_k<0><<<dim3(8, 16, 12), 256, SM_PIPE>>>(nullptr, nullptr);

    fused_attn7_k<<<dim3(32, H_, B_), 256, SM_FUSED>>>(out2);

    hgemm_k<3><<<dim3(8, 16, 1), 256, SM_PIPE>>>(out, bo);
}

// round 17
// speedup vs baseline: 1.1304x; 1.0298x over previous
#include <cuda_runtime.h>
#include <cuda_fp16.h>
#include <cstdint>

#define S_ 4
#define B_ 2
#define N_ 1024
#define D_ 1024
#define H_ 16
#define DH_ 64

// ---------------- device scratch (no allocations allowed) -------------------
__device__ __half g_xh[B_ * N_ * D_];                       // 4MB
__device__ __half g_wh[13 * 1024 * 1024];                   // Wq(0-3) Wk(4-7) Wv(8-11) Wo(12)
__device__ __half g_qh[S_ * B_ * N_ * D_];                  // 16MB (pre-scaled by alpha)
__device__ __half g_kh[S_ * B_ * N_ * D_];                  // 16MB
__device__ __half g_vh[S_ * B_ * N_ * D_];                  // 16MB
__device__ __half g_combh[B_ * N_ * D_];                    // 4MB
__device__ float g_meanx[B_ * D_];
__device__ float g_scalars[16];  // [0..7]=gw*coh (b*4+s), [8..11]=gw/H, [12]=scale/temp

// ---------------- helpers ----------------------------------------------------
__device__ __forceinline__ uint32_t smem_u32(const void* p) {
    uint32_t a;
    asm("{ .reg .u64 t; cvta.to.shared.u64 t, %1; cvt.u32.u64 %0, t; }" : "=r"(a) : "l"(p));
    return a;
}
// L2-only async copy (bypass L1): copies are single-use streaming
__device__ __forceinline__ void cp16g(uint32_t dst, const __half* src) {
    asm volatile("cp.async.cg.shared.global [%0], [%1], 16;" :: "r"(dst), "l"(src) : "memory");
}
__device__ __forceinline__ void ldm4(uint32_t* r, uint32_t addr) {
    asm volatile("ldmatrix.sync.aligned.m8n8.x4.shared.b16 {%0,%1,%2,%3}, [%4];"
        : "=r"(r[0]), "=r"(r[1]), "=r"(r[2]), "=r"(r[3]) : "r"(addr));
}
__device__ __forceinline__ void ldm2t(uint32_t* r, uint32_t addr) {
    asm volatile("ldmatrix.sync.aligned.m8n8.x2.trans.shared.b16 {%0,%1}, [%2];"
        : "=r"(r[0]), "=r"(r[1]) : "r"(addr));
}
__device__ __forceinline__ void mma16816(float* d, const uint32_t* a, uint32_t b0, uint32_t b1) {
    asm volatile(
        "mma.sync.aligned.m16n8k16.row.col.f32.f16.f16.f32 "
        "{%0,%1,%2,%3}, {%4,%5,%6,%7}, {%8,%9}, {%0,%1,%2,%3};"
        : "+f"(d[0]), "+f"(d[1]), "+f"(d[2]), "+f"(d[3])
        : "r"(a[0]), "r"(a[1]), "r"(a[2]), "r"(a[3]), "r"(b0), "r"(b1));
}
__device__ __forceinline__ uint32_t h2u(__half2 h) { return *(uint32_t*)&h; }
__device__ __forceinline__ __half2 u2h(uint32_t u) { return *(__half2*)&u; }

// ---------------- merged prep (fp16 round) + colmean + amean zero ------------
__global__ void prepcol_k(const float* __restrict__ x, const float* __restrict__ Wq,
                          const float* __restrict__ Wk, const float* __restrict__ Wv,
                          const float* __restrict__ Wo, float* __restrict__ out2) {
    __shared__ float part[8][33];
    if (blockIdx.x < 15360) {
        long long idx = ((long long)blockIdx.x * 256 + threadIdx.x) * 4;
        const float* src; __half* dst; long long off;
        if (idx < 2097152)        { src = x;  off = idx;            dst = g_xh; }
        else if (idx < 6291456)   { src = Wq; off = idx - 2097152;  dst = g_wh; }
        else if (idx < 10485760)  { src = Wk; off = idx - 6291456;  dst = g_wh + 4194304; }
        else if (idx < 14680064)  { src = Wv; off = idx - 10485760; dst = g_wh + 8388608; }
        else                      { src = Wo; off = idx - 14680064; dst = g_wh + 12582912; }
        float4 v = *(const float4*)(src + off);
        __half2 h0 = __floats2half2_rn(v.x, v.y), h1 = __floats2half2_rn(v.z, v.w);
        uint2 o; o.x = h2u(h0); o.y = h2u(h1);
        *(uint2*)(dst + off) = o;
    } else if (blockIdx.x < 15424) {
        int bid = blockIdx.x - 15360;
        int col = bid * 32 + (threadIdx.x & 31);
        int chunk = threadIdx.x >> 5;
        int b = col >> 10, d = col & 1023;
        float sum = 0.f;
        const float* xp = x + (long long)b * N_ * D_ + d + (long long)(chunk * 128) * D_;
        #pragma unroll 8
        for (int n = 0; n < 128; n++) sum += xp[(long long)n * D_];
        part[chunk][threadIdx.x & 31] = sum;
        __syncthreads();
        if (threadIdx.x < 32) {
            float s = 0.f;
            #pragma unroll
            for (int c = 0; c < 8; c++) s += part[c][threadIdx.x];
            g_meanx[bid * 32 + threadIdx.x] = s * (1.0f / N_);
        }
    } else {
        long long idx = ((long long)(blockIdx.x - 15424) * 256 + threadIdx.x) * 4;
        *(float4*)(out2 + idx) = make_float4(0.f, 0.f, 0.f, 0.f);
    }
}

// ---------------- gate: coh, gw, fused scalars ------------------------------
__global__ void gate_k(const float* __restrict__ Wg, const float* __restrict__ bg,
                       const float* __restrict__ hyp_w, const float* __restrict__ temp_p) {
    __shared__ float cohs[8];
    int tid = threadIdx.x;
    int w = tid >> 5, lane = tid & 31;
    if (w < 8) {
        int b = w >> 2, s = w & 3;
        float sum = 0.f;
        for (int d = lane; d < D_; d += 32)
            sum += g_meanx[b * D_ + d] * Wg[s * D_ + d];
        for (int o = 16; o; o >>= 1) sum += __shfl_xor_sync(0xffffffffu, sum, o);
        if (lane == 0) cohs[w] = 1.0f / (1.0f + expf(-(sum + bg[s])));
    }
    __syncthreads();
    if (tid == 0) {
        float t = fminf(fmaxf(temp_p[0], 0.1f), 10.0f);
        float e[S_], mx = -1e30f;
        for (int s = 0; s < S_; s++) { e[s] = hyp_w[s] / t; mx = fmaxf(mx, e[s]); }
        float den = 0.f;
        for (int s = 0; s < S_; s++) { e[s] = expf(e[s] - mx); den += e[s]; }
        for (int s = 0; s < S_; s++) {
            float gw = e[s] / den;
            g_scalars[8 + s] = gw / (float)H_;
            for (int b = 0; b < B_; b++)
                g_scalars[b * 4 + s] = gw * cohs[b * 4 + s];
        }
        g_scalars[12] = 0.125f / t;   // DH^-0.5 / temp (folded into Q proj)
    }
}

// ---------------- fp16 HMMA GEMM (projections): 2-stage (R8-proven) ---------
// MODE 0: QKV proj (Q pre-scaled by g_scalars[12]). MODE 3: out proj.
template<int MODE>
__global__ void __launch_bounds__(256) hgemm_k(float* __restrict__ outp,
                                               const float* __restrict__ bias)
{
    constexpr int STAGE = 256 * 128;
    extern __shared__ char smem[];
    uint32_t smb = smem_u32(smem);

    int tid = threadIdx.x, lane = tid & 31, wid = tid >> 5;
    int warpM = wid & 3, warpN = wid >> 2;
    int n0 = blockIdx.x * 128, m0 = blockIdx.y * 128, z = blockIdx.z;

    const __half *Ag, *Bg;
    if (MODE == 0) { Ag = g_xh; Bg = g_wh + ((long long)z << 20); }
    else           { Ag = g_combh; Bg = g_wh + (12LL << 20); }

    float acc[2][8][4];
    #pragma unroll
    for (int mf = 0; mf < 2; mf++)
        #pragma unroll
        for (int nf = 0; nf < 8; nf++)
            #pragma unroll
            for (int i = 0; i < 4; i++) acc[mf][nf][i] = 0.f;

    auto issue = [&](int t) {
        const __half* ap = Ag + (long long)m0 * 1024 + t * 64;
        const __half* bp = Bg + (long long)n0 * 1024 + t * 64;
        uint32_t sa  = smb + (t & 1) * STAGE;
        uint32_t sbb = sa + 128 * 128;
        #pragma unroll
        for (int i = 0; i < 4; i++) {
            int c = tid + 256 * i, row = c >> 3, ch = c & 7;
            cp16g(sa + ((row * 128 + ch * 16) ^ ((row & 7) << 4)),
                  ap + (long long)row * 1024 + ch * 8);
        }
        #pragma unroll
        for (int i = 0; i < 4; i++) {
            int c = tid + 256 * i, row = c >> 3, ch = c & 7;
            cp16g(sbb + ((row * 128 + ch * 16) ^ ((row & 7) << 4)),
                  bp + (long long)row * 1024 + ch * 8);
        }
        asm volatile("cp.async.commit_group;" ::: "memory");
    };

    issue(0);
    for (int t = 0; t < 16; t++) {
        if (t + 1 < 16) {
            issue(t + 1);
            asm volatile("cp.async.wait_group 1;" ::: "memory");
        } else {
            asm volatile("cp.async.wait_group 0;" ::: "memory");
        }
        __syncthreads();
        uint32_t sa = smb + (t & 1) * STAGE, sbb = sa + 128 * 128;
        #pragma unroll
        for (int kk = 0; kk < 4; kk++) {
            uint32_t af[2][4], bf[4][4];
            #pragma unroll
            for (int mf = 0; mf < 2; mf++) {
                int row = warpM * 32 + mf * 16 + (lane & 15);
                uint32_t off = row * 128 + kk * 32 + ((lane >> 4) << 4);
                ldm4(af[mf], sa + (off ^ ((row & 7) << 4)));
            }
            #pragma unroll
            for (int nb = 0; nb < 4; nb++) {
                int row = warpN * 64 + nb * 16 + (lane & 15);
                uint32_t off = row * 128 + kk * 32 + ((lane >> 4) << 4);
                ldm4(bf[nb], sbb + (off ^ ((row & 7) << 4)));
            }
            #pragma unroll
            for (int mf = 0; mf < 2; mf++)
                #pragma unroll
                for (int nf = 0; nf < 8; nf++)
                    mma16816(acc[mf][nf], af[mf], bf[nf >> 1][nf & 1], bf[nf >> 1][(nf & 1) + 2]);
        }
        __syncthreads();
    }

    int r4 = lane >> 2, c4l = lane & 3;
    if (MODE == 0) {
        int w_ = z >> 2, s_ = z & 3;
        float qs = (w_ == 0) ? g_scalars[12] : 1.0f;   // fold alpha into Q
        __half* C = (w_ == 0 ? g_qh : (w_ == 1 ? g_kh : g_vh)) + ((long long)s_ << 21);
        #pragma unroll
        for (int mf = 0; mf < 2; mf++)
            #pragma unroll
            for (int nf = 0; nf < 8; nf++)
                #pragma unroll
                for (int hf = 0; hf < 2; hf++) {
                    int row = m0 + warpM * 32 + mf * 16 + r4 + hf * 8;
                    int col = n0 + warpN * 64 + nf * 8 + c4l * 2;
                    __half2 hv = __floats2half2_rn(acc[mf][nf][hf * 2] * qs,
                                                   acc[mf][nf][hf * 2 + 1] * qs);
                    *(__half2*)(C + (long long)row * 1024 + col) = hv;
                }
    } else {
        #pragma unroll
        for (int mf = 0; mf < 2; mf++)
            #pragma unroll
            for (int nf = 0; nf < 8; nf++)
                #pragma unroll
                for (int hf = 0; hf < 2; hf++) {
                    int row = m0 + warpM * 32 + mf * 16 + r4 + hf * 8;
                    int col = n0 + warpN * 64 + nf * 8 + c4l * 2;
                    float2 o;
                    o.x = acc[mf][nf][hf * 2]     + bias[col];
                    o.y = acc[mf][nf][hf * 2 + 1] + bias[col + 1];
                    *(float2*)(outp + (long long)row * 1024 + col) = o;
                }
    }
}

// ---------------- fused attention v10: 256-row KV tiles, 3-slot ring --------
// grid (32, 16, 2) = (it, h, b), 256 threads.
// smem: STRIP 64K | AMEH 66,048 | RING 3x32K (98,304) | lred 1152 | linv 128
//     = 231,168 B (proven fit). Rounds per CTA: 36 (vs 68).
#define AME_SCALE 256.0f
__global__ void __launch_bounds__(256) fused_attn10_k(float* __restrict__ amean_out) {
    extern __shared__ char smem[];
    uint32_t smb = smem_u32(smem);
    const uint32_t STRIP = smb;
    const uint32_t AMEH  = smb + 65536;
    const uint32_t RING  = smb + 131584;
    float* lred = (float*)(smem + 229888);
    float* linv = (float*)(smem + 231040);

    int tid = threadIdx.x, lane = tid & 31, wid = tid >> 5;
    int it = blockIdx.x, h = blockIdx.y, b = blockIdx.z;
    int i0 = it * 32;
    int r4 = lane >> 2, c4l = lane & 3, c2 = c4l * 2;

    for (int i = tid; i < 16512; i += 256)
        asm volatile("st.shared.b32 [%0], %1;" :: "r"(AMEH + i * 4), "r"(0u));
    __syncthreads();

    float oacc[2][8][4];
    #pragma unroll
    for (int mf = 0; mf < 2; mf++)
        #pragma unroll
        for (int nf = 0; nf < 8; nf++)
            #pragma unroll
            for (int i = 0; i < 4; i++) oacc[mf][nf][i] = 0.f;

    // tile stream: g = s*9 + t. t=0 -> Q (4KB); t=1..4 -> K[256-row kt2=t-1];
    // t=5..8 -> V[256-row vt2=t-5]. 32KB ring slots, slot = g % 3.
    auto issue_g = [&](int g) {
        if (g < 36) {
            int s = g / 9, t = g - s * 9;
            long long sbase = ((long long)(s * B_ + b)) << 20;
            uint32_t dst = RING + (uint32_t)(g % 3) * 32768;
            if (t == 0) {
                const __half* src = g_qh + sbase + (long long)i0 * 1024 + h * 64;
                int r = tid >> 3, c = tid & 7;
                cp16g(dst + ((r * 128 + c * 16) ^ ((r & 7) << 4)),
                      src + (long long)r * 1024 + c * 8);
            } else {
                const __half* base = ((t <= 4) ? g_kh : g_vh) + sbase + h * 64;
                int t2 = (t <= 4) ? (t - 1) : (t - 5);
                const __half* src = base + (long long)t2 * 256 * 1024;
                #pragma unroll
                for (int i = 0; i < 8; i++) {
                    int idx = tid + 256 * i, r = idx >> 3, c = idx & 7;
                    cp16g(dst + ((r * 128 + c * 16) ^ ((r & 7) << 4)),
                          src + (long long)r * 1024 + c * 8);
                }
            }
        }
        asm volatile("cp.async.commit_group;" ::: "memory");
    };

    issue_g(0);
    issue_g(1);

    for (int s = 0; s < S_; s++) {
        float ga = g_scalars[8 + s], wsb = g_scalars[b * 4 + s];
        int g0 = s * 9;

        // ---- Q round (gr = g0) ----
        asm volatile("cp.async.wait_group 1;" ::: "memory");
        __syncthreads();
        issue_g(g0 + 2);
        uint32_t qf[4][2][4];
        {
            uint32_t qslot = RING + (uint32_t)(g0 % 3) * 32768;
            #pragma unroll
            for (int kk = 0; kk < 4; kk++)
                #pragma unroll
                for (int mf = 0; mf < 2; mf++) {
                    int r = mf * 16 + (lane & 15);
                    ldm4(qf[kk][mf],
                         qslot + ((r * 128 + kk * 32 + ((lane >> 4) << 4)) ^ ((r & 7) << 4)));
                }
        }

        // ---- SCORE rounds: 4 rounds x 256 j's (two 128-blocks) ----
        float l_part[4] = {0.f, 0.f, 0.f, 0.f};
        for (int kt2 = 0; kt2 < 4; kt2++) {
            int gr = g0 + 1 + kt2;
            asm volatile("cp.async.wait_group 1;" ::: "memory");
            __syncthreads();
            issue_g(gr + 2);
            uint32_t kb = RING + (uint32_t)(gr % 3) * 32768;
            #pragma unroll
            for (int jb = 0; jb < 2; jb++) {
                int jt = kt2 * 2 + jb;
                float sacc[2][2][4];
                #pragma unroll
                for (int mf = 0; mf < 2; mf++)
                    #pragma unroll
                    for (int nb = 0; nb < 2; nb++)
                        #pragma unroll
                        for (int i = 0; i < 4; i++) sacc[mf][nb][i] = 0.f;
                #pragma unroll
                for (int kk = 0; kk < 4; kk++) {
                    uint32_t bf[4];
                    int r = jb * 128 + wid * 16 + (lane & 15);
                    ldm4(bf, kb + ((r * 128 + kk * 32 + ((lane >> 4) << 4)) ^ ((r & 7) << 4)));
                    #pragma unroll
                    for (int mf = 0; mf < 2; mf++) {
                        mma16816(sacc[mf][0], qf[kk][mf], bf[0], bf[2]);
                        mma16816(sacc[mf][1], qf[kk][mf], bf[1], bf[3]);
                    }
                }
                #pragma unroll
                for (int mf = 0; mf < 2; mf++)
                    #pragma unroll
                    for (int nb = 0; nb < 2; nb++)
                        #pragma unroll
                        for (int hf = 0; hf < 2; hf++) {
                            float e0 = __expf(sacc[mf][nb][hf * 2]);
                            float e1 = __expf(sacc[mf][nb][hf * 2 + 1]);
                            l_part[mf * 2 + hf] += e0 + e1;
                            int row = mf * 16 + r4 + hf * 8;
                            uint32_t byte = (uint32_t)((jt * 128 + wid * 16 + nb * 8 + c2) * 2);
                            asm volatile("st.shared.b32 [%0], %1;"
                                :: "r"(STRIP + row * 2048 + (byte ^ ((row & 7) << 4))),
                                   "r"(h2u(__floats2half2_rn(e0, e1))));
                        }
            }
        }

        // ---- l reduce ----
        #pragma unroll
        for (int i = 0; i < 4; i++) {
            l_part[i] += __shfl_xor_sync(0xffffffffu, l_part[i], 1);
            l_part[i] += __shfl_xor_sync(0xffffffffu, l_part[i], 2);
        }
        if (c4l == 0)
            #pragma unroll
            for (int i = 0; i < 4; i++) lred[(i * 8 + r4) * 9 + wid] = l_part[i];
        __syncthreads();
        if (tid < 32) {
            float sm = 0.f;
            #pragma unroll
            for (int w = 0; w < 8; w++) sm += lred[tid * 9 + w];
            linv[tid] = 1.0f / sm;
        }
        __syncthreads();

        __half2 sc[2][2], gah[2][2];
        #pragma unroll
        for (int mf = 0; mf < 2; mf++) {
            float li0 = linv[mf * 16 + r4], li1 = linv[mf * 16 + r4 + 8];
            sc[mf][0]  = __float2half2_rn(wsb * li0);
            sc[mf][1]  = __float2half2_rn(wsb * li1);
            gah[mf][0] = __float2half2_rn(ga * li0 * AME_SCALE);
            gah[mf][1] = __float2half2_rn(ga * li1 * AME_SCALE);
        }

        // ---- PV rounds: 4 rounds x 256 j's; warp owns jloc = wid*16 / block
        int jloc = wid * 16;
        for (int vt2 = 0; vt2 < 4; vt2++) {
            int gr = g0 + 5 + vt2;
            asm volatile("cp.async.wait_group 1;" ::: "memory");
            __syncthreads();
            issue_g(gr + 2);
            uint32_t vb = RING + (uint32_t)(gr % 3) * 32768;
            #pragma unroll
            for (int jb = 0; jb < 2; jb++) {
                int jtg = vt2 * 2 + jb;
                uint32_t af[2][4];
                #pragma unroll
                for (int mf = 0; mf < 2; mf++) {
                    int r = mf * 16 + (lane & 15);
                    uint32_t byte = (uint32_t)((jtg * 128 + jloc) * 2) + ((lane >> 4) << 4);
                    ldm4(af[mf], STRIP + r * 2048 + (byte ^ ((r & 7) << 4)));
                }
                #pragma unroll
                for (int mf = 0; mf < 2; mf++) {
                    int row0 = mf * 16 + r4, row1 = row0 + 8;
                    int colb = jtg * 128 + jloc + c2;
                    uint32_t a00 = AMEH + (uint32_t)(row0 * 1032 + colb) * 2;
                    uint32_t a10 = AMEH + (uint32_t)(row1 * 1032 + colb) * 2;
                    uint32_t old;
                    asm volatile("ld.shared.b32 %0, [%1];" : "=r"(old) : "r"(a00));
                    asm volatile("st.shared.b32 [%0], %1;" :: "r"(a00),
                        "r"(h2u(__hfma2(u2h(af[mf][0]), gah[mf][0], u2h(old)))));
                    asm volatile("ld.shared.b32 %0, [%1];" : "=r"(old) : "r"(a10));
                    asm volatile("st.shared.b32 [%0], %1;" :: "r"(a10),
                        "r"(h2u(__hfma2(u2h(af[mf][1]), gah[mf][1], u2h(old)))));
                    asm volatile("ld.shared.b32 %0, [%1];" : "=r"(old) : "r"(a00 + 16));
                    asm volatile("st.shared.b32 [%0], %1;" :: "r"(a00 + 16),
                        "r"(h2u(__hfma2(u2h(af[mf][2]), gah[mf][0], u2h(old)))));
                    asm volatile("ld.shared.b32 %0, [%1];" : "=r"(old) : "r"(a10 + 16));
                    asm volatile("st.shared.b32 [%0], %1;" :: "r"(a10 + 16),
                        "r"(h2u(__hfma2(u2h(af[mf][3]), gah[mf][1], u2h(old)))));
                }
                #pragma unroll
                for (int mf = 0; mf < 2; mf++) {
                    af[mf][0] = h2u(__hmul2(u2h(af[mf][0]), sc[mf][0]));
                    af[mf][1] = h2u(__hmul2(u2h(af[mf][1]), sc[mf][1]));
                    af[mf][2] = h2u(__hmul2(u2h(af[mf][2]), sc[mf][0]));
                    af[mf][3] = h2u(__hmul2(u2h(af[mf][3]), sc[mf][1]));
                }
                int kr = jb * 128 + jloc + (lane & 7) + ((lane >> 3) & 1) * 8;
                #pragma unroll
                for (int nf = 0; nf < 8; nf++) {
                    uint32_t bf[2];
                    ldm2t(bf, vb + ((kr * 128 + nf * 16) ^ ((kr & 7) << 4)));
                    #pragma unroll
                    for (int mf = 0; mf < 2; mf++)
                        mma16816(oacc[mf][nf], af[mf], bf[0], bf[1]);
                }
            }
        }
    } // s
    __syncthreads();

    // ---- O: 8 warp partials by logical (row,col), flat reduce ----
    {
        float* scr = (float*)(smem + 131584);   // ring dead, 96KB available
        #pragma unroll
        for (int mf = 0; mf < 2; mf++)
            #pragma unroll
            for (int nf = 0; nf < 8; nf++)
                #pragma unroll
                for (int i = 0; i < 4; i++) {
                    int row = mf * 16 + r4 + (i >> 1) * 8;
                    int col = nf * 8 + c2 + (i & 1);
                    scr[wid * 2048 + row * 64 + col] = oacc[mf][nf][i];
                }
        __syncthreads();
        int row = tid >> 3, colg = (tid & 7) * 8;
        #pragma unroll
        for (int c = 0; c < 8; c += 2) {
            float v0 = 0.f, v1 = 0.f;
            #pragma unroll
            for (int w = 0; w < 8; w++) {
                v0 += scr[w * 2048 + row * 64 + colg + c];
                v1 += scr[w * 2048 + row * 64 + colg + c + 1];
            }
            __half2 hv = __floats2half2_rn(v0, v1);
            *(__half2*)(g_combh + ((long long)b << 20)
                        + (long long)(i0 + row) * 1024 + h * 64 + colg + c) = hv;
        }
    }

    // ---- amean flush: fp16(x256) -> f32 red.add ----
    {
        const float inv_s = 1.0f / AME_SCALE;
        for (int i = tid; i < 8192; i += 256) {
            int row = i >> 8, cc = (i & 255) * 4;
            uint2 u;
            asm volatile("ld.shared.v2.b32 {%0,%1}, [%2];"
                : "=r"(u.x), "=r"(u.y) : "r"(AMEH + (uint32_t)(row * 1032 + cc) * 2));
            float2 f0 = __half22float2(u2h(u.x)), f1 = __half22float2(u2h(u.y));
            float* dst = amean_out + ((long long)(b * 1024 + i0 + row)) * 1024 + cc;
            asm volatile("red.global.add.f32 [%0], %1;" :: "l"(dst),     "f"(f0.x * inv_s));
            asm volatile("red.global.add.f32 [%0], %1;" :: "l"(dst + 1), "f"(f0.y * inv_s));
            asm volatile("red.global.add.f32 [%0], %1;" :: "l"(dst + 2), "f"(f1.x * inv_s));
            asm volatile("red.global.add.f32 [%0], %1;" :: "l"(dst + 3), "f"(f1.y * inv_s));
        }
    }
}

// ---------------- launch ----------------------------------------------------
extern "C" void kernel_launch(void* const* d_in, const int* in_sizes, int n_in,
                              void* d_out, int out_size) {
    const float* x     = (const float*)d_in[0];
    const float* Wq    = (const float*)d_in[1];
    const float* Wk    = (const float*)d_in[2];
    const float* Wv    = (const float*)d_in[3];
    const float* Wg    = (const float*)d_in[4];
    const float* bg    = (const float*)d_in[5];
    const float* Wo    = (const float*)d_in[6];
    const float* bo    = (const float*)d_in[7];
    const float* hyp_w = (const float*)d_in[8];
    const float* temp  = (const float*)d_in[9];
    float* out = (float*)d_out;
    float* out2 = out + (long long)B_ * N_ * D_;

    const int SM_PIPE  = 65536;
    const int SM_FUSED = 231168;

    cudaFuncSetAttribute(hgemm_k<0>, cudaFuncAttributeMaxDynamicSharedMemorySize, SM_PIPE);
    cudaFuncSetAttribute(hgemm_k<3>, cudaFuncAttributeMaxDynamicSharedMemorySize, SM_PIPE);
    cudaFuncSetAttribute(fused_attn10_k, cudaFuncAttributeMaxDynamicSharedMemorySize, SM_FUSED);

    prepcol_k<<<17472, 256>>>(x, Wq, Wk, Wv, Wo, out2);
    gate_k<<<1, 256>>>(Wg, bg, hyp_w, temp);

    hgemm_k<0><<<dim3(8, 16, 12), 256, SM_PIPE>>>(nullptr, nullptr);

    fused_attn10_k<<<dim3(32, H_, B_), 256, SM_FUSED>>>(out2);

    hgemm_k<3><<<dim3(8, 16, 1), 256, SM_PIPE>>>(out, bo);
}